// round 1
// baseline (speedup 1.0000x reference)
#include <cuda_runtime.h>
#include <cstdint>

// ---------------- scratch (no allocations allowed) ----------------
struct Scratch {
    float t[16 * 768];      // pre-softmax GEMM1 output
    float yfa[16 * 768];    // fast_attention output (stage 2)
    float cat[16 * 768];    // dumped concatenated input (aux for stage-2 epilogue)
    float rall[16 * 768];   // gathered memory rows: [b][i][k], ld=768
    float rcur[16 * 256];   // updated r
    float m[16 * 256];      // recurrent m
    float updw[48];         // sigmoid update weights [b*3+i]
    float readw[48];        // tanh(max) read weights [b*3+i]
    unsigned long long pack[48]; // packed (orderable_max << 32 | ~idx)
};
__device__ Scratch g_s;

__device__ __forceinline__ unsigned int forder(float f) {
    unsigned int u = __float_as_uint(f);
    return (u & 0x80000000u) ? ~u : (u | 0x80000000u);
}
__device__ __forceinline__ float forder_inv(unsigned int u) {
    unsigned int v = (u & 0x80000000u) ? (u & 0x7FFFFFFFu) : ~u;
    return __uint_as_float(v);
}

__global__ void init_kernel() {
    int t = threadIdx.x;
    if (t < 48) g_s.pack[t] = 0ull;
    for (int i = t; i < 16 * 256; i += blockDim.x) g_s.m[i] = 0.f;
}

// ---------------- generic 16-row fused GEMM ----------------
// Y[b, j] = epilogue( softmax?(concat(Xa,Xb))[b,:] @ W[:, j] + bias[j] )
// One block handles TJ output columns for ALL 16 batch rows.
// EPI: 0 plain, 1 y = aux*v (fast_attention stage 2),
//      2 r-update: y = u*relu(v) + (1-u)*aux  (u = scal[b*3]),
//      3 m-update: y = scal[b*3]*relu(v), optional tanh to out2.
template <int TJ, int KSPLIT, int EPI, bool SMAX>
__global__ void gemm16(const float* __restrict__ Xa, int lda, int Ka,
                       const float* __restrict__ Xb, int ldb, int Kb,
                       const float* __restrict__ W, const float* __restrict__ bias, int N,
                       float* __restrict__ Y, int ldy,
                       const float* __restrict__ aux, int ldaux,
                       const float* __restrict__ scal,
                       float* __restrict__ dump,
                       float* __restrict__ out2) {
    constexpr int NT = TJ * KSPLIT;
    extern __shared__ float xs[];           // 16*K floats
    __shared__ float part[NT * 17];
    __shared__ float rmax[16], rsum[16];

    const int tid = threadIdx.x;
    const int K = Ka + Kb;

    // load (concatenated) X into smem, all 16 rows
    for (int b = 0; b < 16; b++)
        for (int k = tid; k < K; k += NT) {
            float v = (k < Ka) ? Xa[b * lda + k] : Xb[b * ldb + (k - Ka)];
            xs[b * K + k] = v;
        }
    __syncthreads();

    if (dump != nullptr && blockIdx.x == 0) {
        for (int b = 0; b < 16; b++)
            for (int k = tid; k < K; k += NT) dump[b * K + k] = xs[b * K + k];
    }

    if (SMAX) {
        int warp = tid >> 5, lane = tid & 31;
        for (int b = warp; b < 16; b += NT / 32) {
            float mx = -3.4e38f;
            for (int k = lane; k < K; k += 32) mx = fmaxf(mx, xs[b * K + k]);
            #pragma unroll
            for (int o = 16; o > 0; o >>= 1) mx = fmaxf(mx, __shfl_xor_sync(0xffffffffu, mx, o));
            float s = 0.f;
            for (int k = lane; k < K; k += 32) s += __expf(xs[b * K + k] - mx);
            #pragma unroll
            for (int o = 16; o > 0; o >>= 1) s += __shfl_xor_sync(0xffffffffu, s, o);
            if (lane == 0) { rmax[b] = mx; rsum[b] = 1.f / s; }
        }
        __syncthreads();
        for (int b = 0; b < 16; b++)
            for (int k = tid; k < K; k += NT)
                xs[b * K + k] = __expf(xs[b * K + k] - rmax[b]) * rsum[b];
        __syncthreads();
    }

    const int jl = tid % TJ;
    const int ks = tid / TJ;
    const int j = blockIdx.x * TJ + jl;

    float acc[16];
    #pragma unroll
    for (int b = 0; b < 16; b++) acc[b] = 0.f;

    if (j < N) {
        for (int k0 = ks * 4; k0 < K; k0 += 4 * KSPLIT) {
            float w0 = W[(k0 + 0) * N + j];
            float w1 = W[(k0 + 1) * N + j];
            float w2 = W[(k0 + 2) * N + j];
            float w3 = W[(k0 + 3) * N + j];
            #pragma unroll
            for (int b = 0; b < 16; b++) {
                float4 xv = *reinterpret_cast<const float4*>(xs + b * K + k0);
                acc[b] = fmaf(xv.x, w0, acc[b]);
                acc[b] = fmaf(xv.y, w1, acc[b]);
                acc[b] = fmaf(xv.z, w2, acc[b]);
                acc[b] = fmaf(xv.w, w3, acc[b]);
            }
        }
    }

    #pragma unroll
    for (int b = 0; b < 16; b++) part[(ks * TJ + jl) * 17 + b] = acc[b];
    __syncthreads();
    #pragma unroll
    for (int s = KSPLIT / 2; s > 0; s >>= 1) {
        if (ks < s) {
            #pragma unroll
            for (int b = 0; b < 16; b++) {
                acc[b] += part[((ks + s) * TJ + jl) * 17 + b];
                part[(ks * TJ + jl) * 17 + b] = acc[b];
            }
        }
        __syncthreads();
    }

    if (ks == 0 && j < N) {
        float bv = bias[j];
        #pragma unroll
        for (int b = 0; b < 16; b++) {
            float v = acc[b] + bv;
            if (EPI == 0) {
                Y[b * ldy + j] = v;
            } else if (EPI == 1) {
                Y[b * ldy + j] = aux[b * ldaux + j] * v;
            } else if (EPI == 2) {
                float u = scal[b * 3];
                Y[b * ldy + j] = u * fmaxf(v, 0.f) + (1.f - u) * aux[b * ldaux + j];
            } else {
                float mm = scal[b * 3] * fmaxf(v, 0.f);
                Y[b * ldy + j] = mm;
                if (out2) out2[b * 256 + j] = tanhf(mm);
            }
        }
    }
}

// ---------------- big read GEMM + fused max/argmax ----------------
// z[b, i*10000 + j] = yr[b,:] @ W_read[:, n] + b_read[n]
// pack[b*3+i] = atomicMax over (orderable(z) << 32 | (0xFFFFFFFF - j))
template <int TJ, int KSPLIT>
__global__ void read_argmax_kernel(const float* __restrict__ X,
                                   const float* __restrict__ W,
                                   const float* __restrict__ bias,
                                   unsigned long long* __restrict__ pack) {
    constexpr int NT = TJ * KSPLIT;
    constexpr int K = 512;
    constexpr int NTOT = 30000, NSLOT = 10000;
    extern __shared__ float xs[];
    __shared__ float part[NT * 17];
    __shared__ unsigned long long red2[16 * 2];

    const int tid = threadIdx.x;
    const int i = blockIdx.y;

    for (int b = 0; b < 16; b++)
        for (int k = tid; k < K; k += NT) xs[b * K + k] = X[b * K + k];
    __syncthreads();

    const int jl = tid % TJ, ks = tid / TJ;
    const int j = blockIdx.x * TJ + jl;
    const bool valid = j < NSLOT;
    const int n = i * NSLOT + j;

    float acc[16];
    #pragma unroll
    for (int b = 0; b < 16; b++) acc[b] = 0.f;

    if (valid) {
        for (int k0 = ks * 4; k0 < K; k0 += 4 * KSPLIT) {
            float w0 = W[(k0 + 0) * NTOT + n];
            float w1 = W[(k0 + 1) * NTOT + n];
            float w2 = W[(k0 + 2) * NTOT + n];
            float w3 = W[(k0 + 3) * NTOT + n];
            #pragma unroll
            for (int b = 0; b < 16; b++) {
                float4 xv = *reinterpret_cast<const float4*>(xs + b * K + k0);
                acc[b] = fmaf(xv.x, w0, acc[b]);
                acc[b] = fmaf(xv.y, w1, acc[b]);
                acc[b] = fmaf(xv.z, w2, acc[b]);
                acc[b] = fmaf(xv.w, w3, acc[b]);
            }
        }
    }

    #pragma unroll
    for (int b = 0; b < 16; b++) part[(ks * TJ + jl) * 17 + b] = acc[b];
    __syncthreads();
    #pragma unroll
    for (int s = KSPLIT / 2; s > 0; s >>= 1) {
        if (ks < s) {
            #pragma unroll
            for (int b = 0; b < 16; b++) {
                acc[b] += part[((ks + s) * TJ + jl) * 17 + b];
                part[(ks * TJ + jl) * 17 + b] = acc[b];
            }
        }
        __syncthreads();
    }

    if (ks == 0) {  // tid < TJ (warps 0..TJ/32-1, fully populated)
        float bv = valid ? bias[n] : 0.f;
        #pragma unroll
        for (int b = 0; b < 16; b++) {
            unsigned long long p = 0ull;
            if (valid) {
                float z = acc[b] + bv;
                p = ((unsigned long long)forder(z) << 32) |
                    (unsigned long long)(0xFFFFFFFFu - (unsigned)j);
            }
            #pragma unroll
            for (int o = 16; o > 0; o >>= 1) {
                unsigned long long q = __shfl_down_sync(0xffffffffu, p, o);
                if (q > p) p = q;
            }
            if ((tid & 31) == 0) red2[b * 2 + (tid >> 5)] = p;
        }
    }
    __syncthreads();
    if (tid < 16) {
        unsigned long long p = red2[tid * 2];
        if (red2[tid * 2 + 1] > p) p = red2[tid * 2 + 1];
        atomicMax(&pack[tid * 3 + i], p);
    }
}

// ---------------- update-weight sigmoid + unpack + gather ----------------
__global__ void uwgather_kernel(const float* __restrict__ yu,
                                const float* __restrict__ W_uw,
                                const float* __restrict__ b_uw,
                                const float* __restrict__ memory) {
    __shared__ int sidx[48];
    int t = threadIdx.x;
    if (t < 48) {
        int b = t / 3, i = t % 3;
        float acc = 0.f;
        #pragma unroll 8
        for (int k = 0; k < 512; k++) acc = fmaf(yu[b * 512 + k], W_uw[k * 3 + i], acc);
        acc += b_uw[i];
        g_s.updw[t] = 1.f / (1.f + __expf(-acc));
        unsigned long long p = g_s.pack[t];
        unsigned int idx = 0xFFFFFFFFu - (unsigned)(p & 0xFFFFFFFFull);
        float z = forder_inv((unsigned)(p >> 32));
        g_s.readw[t] = tanhf(z);
        sidx[t] = (int)idx;
    }
    __syncthreads();
    for (int u = t; u < 48 * 256; u += blockDim.x) {
        int b = u / 768;
        int rem = u - b * 768;
        int i = rem >> 8;
        int k = rem & 255;
        long src = ((long)b * 10000 + sidx[b * 3 + i]) * 256 + k;
        g_s.rall[u] = memory[src];
    }
}

// ---------------- host launcher ----------------
extern "C" void kernel_launch(void* const* d_in, const int* in_sizes, int n_in,
                              void* d_out, int out_size) {
    const float* inputs = (const float*)d_in[0];
    const float* memory = (const float*)d_in[1];
    const float* r_w1 = (const float*)d_in[2];
    const float* r_b1 = (const float*)d_in[3];
    const float* r_w2 = (const float*)d_in[4];
    const float* r_b2 = (const float*)d_in[5];
    const float* W_read = (const float*)d_in[6];
    const float* b_read = (const float*)d_in[7];
    const float* u_w1 = (const float*)d_in[8];
    const float* u_b1 = (const float*)d_in[9];
    const float* u_w2 = (const float*)d_in[10];
    const float* u_b2 = (const float*)d_in[11];
    const float* W_uw = (const float*)d_in[12];
    const float* b_uw = (const float*)d_in[13];
    const float* um_w1 = (const float*)d_in[14];
    const float* um_b1 = (const float*)d_in[15];
    const float* um_w2 = (const float*)d_in[16];
    const float* um_b2 = (const float*)d_in[17];
    const float* W_um = (const float*)d_in[18];
    const float* b_um = (const float*)d_in[19];
    const float* am_w1 = (const float*)d_in[20];
    const float* am_b1 = (const float*)d_in[21];
    const float* am_w2 = (const float*)d_in[22];
    const float* am_b2 = (const float*)d_in[23];
    const float* W_am = (const float*)d_in[24];
    const float* b_am = (const float*)d_in[25];
    float* out = (float*)d_out;

    Scratch* S = nullptr;
    cudaGetSymbolAddress((void**)&S, g_s);

    const int DSM = 16 * 768 * 4;  // max dynamic smem we use
    cudaFuncSetAttribute(gemm16<8, 32, 0, false>, cudaFuncAttributeMaxDynamicSharedMemorySize, DSM);
    cudaFuncSetAttribute(gemm16<8, 32, 1, true>,  cudaFuncAttributeMaxDynamicSharedMemorySize, DSM);
    cudaFuncSetAttribute(gemm16<8, 32, 2, false>, cudaFuncAttributeMaxDynamicSharedMemorySize, DSM);
    cudaFuncSetAttribute(gemm16<8, 32, 3, false>, cudaFuncAttributeMaxDynamicSharedMemorySize, DSM);
    cudaFuncSetAttribute(read_argmax_kernel<64, 4>, cudaFuncAttributeMaxDynamicSharedMemorySize, DSM);

    const int SM512 = 16 * 512 * 4;
    const int SM768 = 16 * 768 * 4;

    init_kernel<<<1, 256>>>();

    // fa_r: yfa = inputs * (softmax(inputs@r_w1+b1) @ r_w2 + b2)
    gemm16<8, 32, 0, false><<<64, 256, SM512>>>(inputs, 512, 512, nullptr, 0, 0,
        r_w1, r_b1, 512, S->t, 512, nullptr, 0, nullptr, nullptr, nullptr);
    gemm16<8, 32, 1, true><<<64, 256, SM512>>>(S->t, 512, 512, nullptr, 0, 0,
        r_w2, r_b2, 512, S->yfa, 512, inputs, 512, nullptr, nullptr, nullptr);

    // big read GEMM + fused max/argmax
    read_argmax_kernel<64, 4><<<dim3(157, 3, 1), 256, SM512>>>(S->yfa, W_read, b_read, S->pack);

    // fa_u
    gemm16<8, 32, 0, false><<<64, 256, SM512>>>(inputs, 512, 512, nullptr, 0, 0,
        u_w1, u_b1, 512, S->t, 512, nullptr, 0, nullptr, nullptr, nullptr);
    gemm16<8, 32, 1, true><<<64, 256, SM512>>>(S->t, 512, 512, nullptr, 0, 0,
        u_w2, u_b2, 512, S->yfa, 512, inputs, 512, nullptr, nullptr, nullptr);

    // upd_w sigmoid + unpack read_w/idx + gather memory rows
    uwgather_kernel<<<1, 256>>>(S->yfa, W_uw, b_uw, memory);

    for (int i = 0; i < 3; i++) {
        // fa_um on concat(r_i, inputs)  (dump cat for stage-2 epilogue)
        gemm16<8, 32, 0, false><<<96, 256, SM768>>>(S->rall + i * 256, 768, 256,
            inputs, 512, 512, um_w1, um_b1, 768, S->t, 768, nullptr, 0, nullptr, S->cat, nullptr);
        gemm16<8, 32, 1, true><<<96, 256, SM768>>>(S->t, 768, 768, nullptr, 0, 0,
            um_w2, um_b2, 768, S->yfa, 768, S->cat, 768, nullptr, nullptr, nullptr);
        // upd + r update
        gemm16<8, 32, 2, false><<<32, 256, SM768>>>(S->yfa, 768, 768, nullptr, 0, 0,
            W_um, b_um, 256, S->rcur, 256, S->rall + i * 256, 768, S->updw + i, nullptr, nullptr);
        // fa_am on concat(r, m)
        gemm16<8, 32, 0, false><<<64, 256, SM512>>>(S->rcur, 256, 256, S->m, 256, 256,
            am_w1, am_b1, 512, S->t, 512, nullptr, 0, nullptr, S->cat, nullptr);
        gemm16<8, 32, 1, true><<<64, 256, SM512>>>(S->t, 512, 512, nullptr, 0, 0,
            am_w2, am_b2, 512, S->yfa, 512, S->cat, 512, nullptr, nullptr, nullptr);
        // m update (+ final tanh to out on last iteration)
        gemm16<8, 32, 3, false><<<32, 256, SM512>>>(S->yfa, 512, 512, nullptr, 0, 0,
            W_am, b_am, 256, S->m, 256, nullptr, 0, S->readw + i, nullptr,
            (i == 2) ? out : nullptr);
    }
}

// round 2
// speedup vs baseline: 1.4494x; 1.4494x over previous
#include <cuda_runtime.h>
#include <cstdint>

// ---------------- scratch (no allocations allowed) ----------------
struct Scratch {
    float t[16 * 768];      // pre-softmax GEMM1 output
    float yfa[16 * 768];    // fast_attention output (stage 2)
    float cat[16 * 768];    // dumped concatenated input (aux for stage-2 epilogue)
    float rall[16 * 768];   // gathered memory rows: [b][i][k], ld=768
    float rcur[16 * 256];   // updated r
    float m[16 * 256];      // recurrent m
    float updw[48];         // sigmoid update weights [b*3+i]
    float readw[48];        // tanh(max) read weights [b*3+i]
    unsigned long long pack[48]; // packed (orderable_max << 32 | ~idx)
};
__device__ Scratch g_s;

__device__ __forceinline__ unsigned int forder(float f) {
    unsigned int u = __float_as_uint(f);
    return (u & 0x80000000u) ? ~u : (u | 0x80000000u);
}
__device__ __forceinline__ float forder_inv(unsigned int u) {
    unsigned int v = (u & 0x80000000u) ? (u & 0x7FFFFFFFu) : ~u;
    return __uint_as_float(v);
}

__global__ void init_kernel() {
    int t = threadIdx.x;
    if (t < 48) g_s.pack[t] = 0ull;
    for (int i = t; i < 16 * 256; i += blockDim.x) g_s.m[i] = 0.f;
}

// ---------------- generic 16-row fused GEMM ----------------
// Y[b, j] = epilogue( softmax?(concat(Xa,Xb))[b,:] @ W[:, j] + bias[j] )
// One block handles TJ output columns for ALL 16 batch rows.
// EPI: 0 plain, 1 y = aux*v (fast_attention stage 2),
//      2 r-update: y = u*relu(v) + (1-u)*aux  (u = scal[b*3]),
//      3 m-update: y = scal[b*3]*relu(v), optional tanh to out2.
template <int TJ, int KSPLIT, int EPI, bool SMAX>
__global__ void gemm16(const float* __restrict__ Xa, int lda, int Ka,
                       const float* __restrict__ Xb, int ldb, int Kb,
                       const float* __restrict__ W, const float* __restrict__ bias, int N,
                       float* __restrict__ Y, int ldy,
                       const float* __restrict__ aux, int ldaux,
                       const float* __restrict__ scal,
                       float* __restrict__ dump,
                       float* __restrict__ out2) {
    constexpr int NT = TJ * KSPLIT;
    extern __shared__ float xs[];           // 16*K floats
    __shared__ float part[NT * 17];
    __shared__ float rmax[16], rsum[16];

    const int tid = threadIdx.x;
    const int K = Ka + Kb;

    // load (concatenated) X into smem, all 16 rows
    for (int b = 0; b < 16; b++)
        for (int k = tid; k < K; k += NT) {
            float v = (k < Ka) ? Xa[b * lda + k] : Xb[b * ldb + (k - Ka)];
            xs[b * K + k] = v;
        }
    __syncthreads();

    if (dump != nullptr && blockIdx.x == 0) {
        for (int b = 0; b < 16; b++)
            for (int k = tid; k < K; k += NT) dump[b * K + k] = xs[b * K + k];
    }

    if (SMAX) {
        int warp = tid >> 5, lane = tid & 31;
        for (int b = warp; b < 16; b += NT / 32) {
            float mx = -3.4e38f;
            for (int k = lane; k < K; k += 32) mx = fmaxf(mx, xs[b * K + k]);
            #pragma unroll
            for (int o = 16; o > 0; o >>= 1) mx = fmaxf(mx, __shfl_xor_sync(0xffffffffu, mx, o));
            float s = 0.f;
            for (int k = lane; k < K; k += 32) s += __expf(xs[b * K + k] - mx);
            #pragma unroll
            for (int o = 16; o > 0; o >>= 1) s += __shfl_xor_sync(0xffffffffu, s, o);
            if (lane == 0) { rmax[b] = mx; rsum[b] = 1.f / s; }
        }
        __syncthreads();
        for (int b = 0; b < 16; b++)
            for (int k = tid; k < K; k += NT)
                xs[b * K + k] = __expf(xs[b * K + k] - rmax[b]) * rsum[b];
        __syncthreads();
    }

    const int jl = tid % TJ;
    const int ks = tid / TJ;
    const int j = blockIdx.x * TJ + jl;

    float acc[16];
    #pragma unroll
    for (int b = 0; b < 16; b++) acc[b] = 0.f;

    if (j < N) {
        for (int k0 = ks * 4; k0 < K; k0 += 4 * KSPLIT) {
            float w0 = W[(k0 + 0) * N + j];
            float w1 = W[(k0 + 1) * N + j];
            float w2 = W[(k0 + 2) * N + j];
            float w3 = W[(k0 + 3) * N + j];
            #pragma unroll
            for (int b = 0; b < 16; b++) {
                float4 xv = *reinterpret_cast<const float4*>(xs + b * K + k0);
                acc[b] = fmaf(xv.x, w0, acc[b]);
                acc[b] = fmaf(xv.y, w1, acc[b]);
                acc[b] = fmaf(xv.z, w2, acc[b]);
                acc[b] = fmaf(xv.w, w3, acc[b]);
            }
        }
    }

    #pragma unroll
    for (int b = 0; b < 16; b++) part[(ks * TJ + jl) * 17 + b] = acc[b];
    __syncthreads();
    #pragma unroll
    for (int s = KSPLIT / 2; s > 0; s >>= 1) {
        if (ks < s) {
            #pragma unroll
            for (int b = 0; b < 16; b++) {
                acc[b] += part[((ks + s) * TJ + jl) * 17 + b];
                part[(ks * TJ + jl) * 17 + b] = acc[b];
            }
        }
        __syncthreads();
    }

    if (ks == 0 && j < N) {
        float bv = bias[j];
        #pragma unroll
        for (int b = 0; b < 16; b++) {
            float v = acc[b] + bv;
            if (EPI == 0) {
                Y[b * ldy + j] = v;
            } else if (EPI == 1) {
                Y[b * ldy + j] = aux[b * ldaux + j] * v;
            } else if (EPI == 2) {
                float u = scal[b * 3];
                Y[b * ldy + j] = u * fmaxf(v, 0.f) + (1.f - u) * aux[b * ldaux + j];
            } else {
                float mm = scal[b * 3] * fmaxf(v, 0.f);
                Y[b * ldy + j] = mm;
                if (out2) out2[b * 256 + j] = tanhf(mm);
            }
        }
    }
}

// ---------------- big read GEMM + fused max/argmax ----------------
// z[b, i*10000 + j] = yr[b,:] @ W_read[:, n] + b_read[n]
// pack[b*3+i] = atomicMax over (orderable(z) << 32 | (0xFFFFFFFF - j))
template <int TJ, int KSPLIT>
__global__ void read_argmax_kernel(const float* __restrict__ X,
                                   const float* __restrict__ W,
                                   const float* __restrict__ bias,
                                   unsigned long long* __restrict__ pack) {
    constexpr int NT = TJ * KSPLIT;
    constexpr int K = 512;
    constexpr int NTOT = 30000, NSLOT = 10000;
    extern __shared__ float xs[];
    __shared__ float part[NT * 17];
    __shared__ unsigned long long red2[16 * 2];

    const int tid = threadIdx.x;
    const int i = blockIdx.y;

    for (int b = 0; b < 16; b++)
        for (int k = tid; k < K; k += NT) xs[b * K + k] = X[b * K + k];
    __syncthreads();

    const int jl = tid % TJ, ks = tid / TJ;
    const int j = blockIdx.x * TJ + jl;
    const bool valid = j < NSLOT;
    const int n = i * NSLOT + j;

    float acc[16];
    #pragma unroll
    for (int b = 0; b < 16; b++) acc[b] = 0.f;

    if (valid) {
        for (int k0 = ks * 4; k0 < K; k0 += 4 * KSPLIT) {
            float w0 = W[(k0 + 0) * NTOT + n];
            float w1 = W[(k0 + 1) * NTOT + n];
            float w2 = W[(k0 + 2) * NTOT + n];
            float w3 = W[(k0 + 3) * NTOT + n];
            #pragma unroll
            for (int b = 0; b < 16; b++) {
                float4 xv = *reinterpret_cast<const float4*>(xs + b * K + k0);
                acc[b] = fmaf(xv.x, w0, acc[b]);
                acc[b] = fmaf(xv.y, w1, acc[b]);
                acc[b] = fmaf(xv.z, w2, acc[b]);
                acc[b] = fmaf(xv.w, w3, acc[b]);
            }
        }
    }

    #pragma unroll
    for (int b = 0; b < 16; b++) part[(ks * TJ + jl) * 17 + b] = acc[b];
    __syncthreads();
    #pragma unroll
    for (int s = KSPLIT / 2; s > 0; s >>= 1) {
        if (ks < s) {
            #pragma unroll
            for (int b = 0; b < 16; b++) {
                acc[b] += part[((ks + s) * TJ + jl) * 17 + b];
                part[(ks * TJ + jl) * 17 + b] = acc[b];
            }
        }
        __syncthreads();
    }

    if (ks == 0) {  // tid < TJ (warps 0..TJ/32-1, fully populated)
        float bv = valid ? bias[n] : 0.f;
        #pragma unroll
        for (int b = 0; b < 16; b++) {
            unsigned long long p = 0ull;
            if (valid) {
                float z = acc[b] + bv;
                p = ((unsigned long long)forder(z) << 32) |
                    (unsigned long long)(0xFFFFFFFFu - (unsigned)j);
            }
            #pragma unroll
            for (int o = 16; o > 0; o >>= 1) {
                unsigned long long q = __shfl_down_sync(0xffffffffu, p, o);
                if (q > p) p = q;
            }
            if ((tid & 31) == 0) red2[b * 2 + (tid >> 5)] = p;
        }
    }
    __syncthreads();
    if (tid < 16) {
        unsigned long long p = red2[tid * 2];
        if (red2[tid * 2 + 1] > p) p = red2[tid * 2 + 1];
        atomicMax(&pack[tid * 3 + i], p);
    }
}

// ---------------- update-weight sigmoid + unpack + gather ----------------
__global__ void uwgather_kernel(const float* __restrict__ yu,
                                const float* __restrict__ W_uw,
                                const float* __restrict__ b_uw,
                                const float* __restrict__ memory) {
    __shared__ int sidx[48];
    int t = threadIdx.x;
    if (t < 48) {
        int b = t / 3, i = t % 3;
        float acc = 0.f;
        #pragma unroll 8
        for (int k = 0; k < 512; k++) acc = fmaf(yu[b * 512 + k], W_uw[k * 3 + i], acc);
        acc += b_uw[i];
        g_s.updw[t] = 1.f / (1.f + __expf(-acc));
        unsigned long long p = g_s.pack[t];
        unsigned int idx = 0xFFFFFFFFu - (unsigned)(p & 0xFFFFFFFFull);
        float z = forder_inv((unsigned)(p >> 32));
        g_s.readw[t] = tanhf(z);
        sidx[t] = (int)idx;
    }
    __syncthreads();
    for (int u = t; u < 48 * 256; u += blockDim.x) {
        int b = u / 768;
        int rem = u - b * 768;
        int i = rem >> 8;
        int k = rem & 255;
        long src = ((long)b * 10000 + sidx[b * 3 + i]) * 256 + k;
        g_s.rall[u] = memory[src];
    }
}

// ---------------- host launcher ----------------
extern "C" void kernel_launch(void* const* d_in, const int* in_sizes, int n_in,
                              void* d_out, int out_size) {
    const float* inputs = (const float*)d_in[0];
    const float* memory = (const float*)d_in[1];
    const float* r_w1 = (const float*)d_in[2];
    const float* r_b1 = (const float*)d_in[3];
    const float* r_w2 = (const float*)d_in[4];
    const float* r_b2 = (const float*)d_in[5];
    const float* W_read = (const float*)d_in[6];
    const float* b_read = (const float*)d_in[7];
    const float* u_w1 = (const float*)d_in[8];
    const float* u_b1 = (const float*)d_in[9];
    const float* u_w2 = (const float*)d_in[10];
    const float* u_b2 = (const float*)d_in[11];
    const float* W_uw = (const float*)d_in[12];
    const float* b_uw = (const float*)d_in[13];
    const float* um_w1 = (const float*)d_in[14];
    const float* um_b1 = (const float*)d_in[15];
    const float* um_w2 = (const float*)d_in[16];
    const float* um_b2 = (const float*)d_in[17];
    const float* W_um = (const float*)d_in[18];
    const float* b_um = (const float*)d_in[19];
    const float* am_w1 = (const float*)d_in[20];
    const float* am_b1 = (const float*)d_in[21];
    const float* am_w2 = (const float*)d_in[22];
    const float* am_b2 = (const float*)d_in[23];
    const float* W_am = (const float*)d_in[24];
    const float* b_am = (const float*)d_in[25];
    float* out = (float*)d_out;

    Scratch* S = nullptr;
    cudaGetSymbolAddress((void**)&S, g_s);

    const int DSM = 16 * 768 * 4;  // max dynamic smem we use
    cudaFuncSetAttribute(gemm16<8, 32, 0, false>, cudaFuncAttributeMaxDynamicSharedMemorySize, DSM);
    cudaFuncSetAttribute(gemm16<8, 32, 1, true>,  cudaFuncAttributeMaxDynamicSharedMemorySize, DSM);
    cudaFuncSetAttribute(gemm16<8, 32, 2, false>, cudaFuncAttributeMaxDynamicSharedMemorySize, DSM);
    cudaFuncSetAttribute(gemm16<8, 32, 3, false>, cudaFuncAttributeMaxDynamicSharedMemorySize, DSM);
    cudaFuncSetAttribute(read_argmax_kernel<64, 4>, cudaFuncAttributeMaxDynamicSharedMemorySize, DSM);

    const int SM512 = 16 * 512 * 4;
    const int SM768 = 16 * 768 * 4;

    init_kernel<<<1, 256>>>();

    // fa_r: yfa = inputs * (softmax(inputs@r_w1+b1) @ r_w2 + b2)
    gemm16<8, 32, 0, false><<<64, 256, SM512>>>(inputs, 512, 512, nullptr, 0, 0,
        r_w1, r_b1, 512, S->t, 512, nullptr, 0, nullptr, nullptr, nullptr);
    gemm16<8, 32, 1, true><<<64, 256, SM512>>>(S->t, 512, 512, nullptr, 0, 0,
        r_w2, r_b2, 512, S->yfa, 512, inputs, 512, nullptr, nullptr, nullptr);

    // big read GEMM + fused max/argmax
    read_argmax_kernel<64, 4><<<dim3(157, 3, 1), 256, SM512>>>(S->yfa, W_read, b_read, S->pack);

    // fa_u
    gemm16<8, 32, 0, false><<<64, 256, SM512>>>(inputs, 512, 512, nullptr, 0, 0,
        u_w1, u_b1, 512, S->t, 512, nullptr, 0, nullptr, nullptr, nullptr);
    gemm16<8, 32, 1, true><<<64, 256, SM512>>>(S->t, 512, 512, nullptr, 0, 0,
        u_w2, u_b2, 512, S->yfa, 512, inputs, 512, nullptr, nullptr, nullptr);

    // upd_w sigmoid + unpack read_w/idx + gather memory rows
    uwgather_kernel<<<1, 256>>>(S->yfa, W_uw, b_uw, memory);

    for (int i = 0; i < 3; i++) {
        // fa_um on concat(r_i, inputs)  (dump cat for stage-2 epilogue)
        gemm16<8, 32, 0, false><<<96, 256, SM768>>>(S->rall + i * 256, 768, 256,
            inputs, 512, 512, um_w1, um_b1, 768, S->t, 768, nullptr, 0, nullptr, S->cat, nullptr);
        gemm16<8, 32, 1, true><<<96, 256, SM768>>>(S->t, 768, 768, nullptr, 0, 0,
            um_w2, um_b2, 768, S->yfa, 768, S->cat, 768, nullptr, nullptr, nullptr);
        // upd + r update
        gemm16<8, 32, 2, false><<<32, 256, SM768>>>(S->yfa, 768, 768, nullptr, 0, 0,
            W_um, b_um, 256, S->rcur, 256, S->rall + i * 256, 768, S->updw + i, nullptr, nullptr);
        // fa_am on concat(r, m)
        gemm16<8, 32, 0, false><<<64, 256, SM512>>>(S->rcur, 256, 256, S->m, 256, 256,
            am_w1, am_b1, 512, S->t, 512, nullptr, 0, nullptr, S->cat, nullptr);
        gemm16<8, 32, 1, true><<<64, 256, SM512>>>(S->t, 512, 512, nullptr, 0, 0,
            am_w2, am_b2, 512, S->yfa, 512, S->cat, 512, nullptr, nullptr, nullptr);
        // m update (+ final tanh to out on last iteration)
        gemm16<8, 32, 3, false><<<32, 256, SM512>>>(S->yfa, 512, 512, nullptr, 0, 0,
            W_am, b_am, 256, S->m, 256, nullptr, 0, S->readw + i, nullptr,
            (i == 2) ? out : nullptr);
    }
}

// round 4
// speedup vs baseline: 1.7534x; 1.2098x over previous
#include <cuda_runtime.h>
#include <cstdint>

// ---------------- scratch (no allocations allowed) ----------------
struct Scratch {
    float tr[16 * 768];     // stage-1 pre-softmax output (reused, max K=768)
    float tu[16 * 512];     // fa_u stage-1
    float yr[16 * 512];     // fa_r output / yam reuse
    float yu[16 * 512];     // fa_u output
    float yum[16 * 768];    // fa_um output
    float rall[16 * 768];   // gathered memory rows [b][i*256+k]
    float rcur[16 * 256];   // updated r
    float m[16 * 256];      // recurrent m
    float updw[48];         // sigmoid update weights [b*3+i]
    float readw[48];        // tanh(max) read weights [b*3+i]
    unsigned long long pack[48];
};
__device__ Scratch g_s;

__device__ unsigned g_cnt = 0;
__device__ volatile unsigned g_gen = 0;

__device__ __forceinline__ void gridbar(int nb) {
    __syncthreads();
    if (threadIdx.x == 0) {
        unsigned gen = g_gen;
        __threadfence();
        if (atomicAdd(&g_cnt, 1) == (unsigned)(nb - 1)) {
            g_cnt = 0;
            __threadfence();
            g_gen = gen + 1;
        } else {
            while (g_gen == gen) { }
        }
    }
    __syncthreads();
}

__device__ __forceinline__ unsigned int forder(float f) {
    unsigned int u = __float_as_uint(f);
    return (u & 0x80000000u) ? ~u : (u | 0x80000000u);
}
__device__ __forceinline__ float forder_inv(unsigned int u) {
    unsigned int v = (u & 0x80000000u) ? (u & 0x7FFFFFFFu) : ~u;
    return __uint_as_float(v);
}
__device__ __forceinline__ unsigned long long pack2(float f) {
    unsigned u = __float_as_uint(f);
    return ((unsigned long long)u << 32) | (unsigned long long)u;
}
__device__ __forceinline__ void ffma2(unsigned long long& acc, unsigned long long x,
                                      unsigned long long w) {
    asm("fma.rn.f32x2 %0, %1, %2, %0;" : "+l"(acc) : "l"(x), "l"(w));
}
__device__ __forceinline__ unsigned long long addf2(unsigned long long a, unsigned long long b) {
    unsigned long long d;
    asm("add.rn.f32x2 %0, %1, %2;" : "=l"(d) : "l"(a), "l"(b));
    return d;
}
__device__ __forceinline__ float lohi(unsigned long long v, int hi) {
    return __uint_as_float(hi ? (unsigned)(v >> 32) : (unsigned)v);
}

// ---------------- generic 16-row fused GEMM phase ----------------
// One j column per warp (16 j per block), k split between lane halves,
// shuffle reduction. All scratch reads via __ldcg (L2-coherent).
// EPI: 0 plain; 1 y = aux*v; 2 y = u*relu(v)+(1-u)*aux (u=scal[b*3]);
//      3 mm = scal[b*3]*relu(v), y=mm, optional tanh(mm) -> out2.
__device__ void gemm_phase(float* sm, int jblk,
                           const float* Xa, int lda, int Ka,
                           const float* Xb, int ldb, int Kb,
                           const float* __restrict__ W,
                           const float* __restrict__ bias, int N,
                           float* Y, int ldy, int EPI, bool SMAX,
                           const float* auxA, int auxlda, int auxKa,
                           const float* auxB, int auxldb,
                           const float* scal, float* out2) {
    const int tid = threadIdx.x;
    const int K = Ka + Kb;
    const int KP = K + 2;   // even pad: banks (2b+k) mod 32, float2-aligned

    for (int idx = tid; idx < 16 * K; idx += 512) {
        int b = idx / K, k = idx - b * K;
        float v = (k < Ka) ? __ldcg(Xa + b * lda + k)
                           : __ldcg(Xb + b * ldb + (k - Ka));
        sm[b * KP + k] = v;
    }
    __syncthreads();

    const int w = tid >> 5, lane = tid & 31;
    if (SMAX) {
        // warp w handles row w
        float mx = -3.4e38f;
        for (int k = lane; k < K; k += 32) mx = fmaxf(mx, sm[w * KP + k]);
        #pragma unroll
        for (int o = 16; o; o >>= 1) mx = fmaxf(mx, __shfl_xor_sync(0xffffffffu, mx, o));
        float s = 0.f;
        for (int k = lane; k < K; k += 32) s += __expf(sm[w * KP + k] - mx);
        #pragma unroll
        for (int o = 16; o; o >>= 1) s += __shfl_xor_sync(0xffffffffu, s, o);
        float inv = 1.f / s;
        for (int k = lane; k < K; k += 32)
            sm[w * KP + k] = __expf(sm[w * KP + k] - mx) * inv;
        __syncthreads();
    }

    const int j = jblk * 16 + w;
    const int b = lane & 15, kh = lane >> 4;
    const int half = K >> 1;
    const float* xrow = sm + b * KP + kh * half;
    const float* Wp = W + (long)(kh * half) * N + j;
    float acc = 0.f;
    #pragma unroll 4
    for (int t2 = 0; t2 < half; t2 += 2) {
        float2 xv = *(const float2*)(xrow + t2);
        float w0 = __ldg(Wp); Wp += N;
        float w1 = __ldg(Wp); Wp += N;
        acc = fmaf(xv.x, w0, acc);
        acc = fmaf(xv.y, w1, acc);
    }
    acc += __shfl_xor_sync(0xffffffffu, acc, 16);

    if (kh == 0) {
        float v = acc + __ldg(bias + j);
        if (EPI == 0) {
            Y[b * ldy + j] = v;
        } else if (EPI == 1) {
            float av = (j < auxKa) ? __ldcg(auxA + b * auxlda + j)
                                   : __ldcg(auxB + b * auxldb + (j - auxKa));
            Y[b * ldy + j] = av * v;
        } else if (EPI == 2) {
            float u = __ldcg(scal + b * 3);
            float av = __ldcg(auxA + b * auxlda + j);
            Y[b * ldy + j] = u * fmaxf(v, 0.f) + (1.f - u) * av;
        } else {
            float mm = __ldcg(scal + b * 3) * fmaxf(v, 0.f);
            Y[b * ldy + j] = mm;
            if (out2) out2[b * 256 + j] = tanhf(mm);
        }
    }
}

// ---------------- big read GEMM + fused max/argmax (FFMA2) ----------------
// 471 tiles of 64 columns (157 per read-slot section i). Per tile: 2 warps
// (k halves of 256). Per lane: 2 j columns, 8 packed b-pair accumulators.
__device__ void read_phase(float* smf, int NB,
                           const float* yr,
                           const float* __restrict__ W,
                           const float* __restrict__ bias,
                           const float* yu,
                           const float* __restrict__ W_uw,
                           const float* __restrict__ b_uw) {
    const int tid = threadIdx.x;
    unsigned long long* xs2 = (unsigned long long*)smf;      // [k][pair] 512*8
    unsigned long long* part = xs2 + 4096;                    // 4 tiles * 32 * 16

    for (int idx = tid; idx < 4096; idx += 512) {
        int p = idx / 512, k = idx - p * 512;
        unsigned lo = __float_as_uint(__ldcg(yr + (2 * p) * 512 + k));
        unsigned hi = __float_as_uint(__ldcg(yr + (2 * p + 1) * 512 + k));
        xs2[k * 8 + p] = ((unsigned long long)hi << 32) | (unsigned long long)lo;
    }
    __syncthreads();

    const int w = tid >> 5, lane = tid & 31;
    const int lt = w >> 1, kh = w & 1;
    const int gtile = blockIdx.x * 4 + lt;
    const bool act = (w < 8) && (gtile < 471);

    int isec = 0, j0 = 0, j1 = 0;
    long n0 = 0, n1 = 0;
    bool v0 = false, v1 = false;
    unsigned long long a0[8], a1[8];

    if (act) {
        isec = gtile / 157;
        int t = gtile - isec * 157;
        j0 = t * 64 + lane; j1 = j0 + 32;
        v0 = j0 < 10000; v1 = j1 < 10000;
        n0 = (long)isec * 10000 + j0; n1 = n0 + 32;
        #pragma unroll
        for (int p = 0; p < 8; p++) { a0[p] = 0ull; a1[p] = 0ull; }

        const float* W0 = W + (long)(kh * 256) * 30000;
        const unsigned long long* xk = xs2 + (kh * 256) * 8;
        #pragma unroll 4
        for (int it = 0; it < 256; it++) {
            float wa = v0 ? __ldg(W0 + n0) : 0.f;
            float wb = v1 ? __ldg(W0 + n1) : 0.f;
            unsigned long long wa2 = pack2(wa), wb2 = pack2(wb);
            #pragma unroll
            for (int p = 0; p < 8; p++) {
                unsigned long long xv = xk[p];
                ffma2(a0[p], xv, wa2);
                ffma2(a1[p], xv, wb2);
            }
            W0 += 30000; xk += 8;
        }
        if (kh == 1) {
            unsigned long long* ps = part + (lt * 32 + lane) * 16;
            #pragma unroll
            for (int p = 0; p < 8; p++) { ps[p] = a0[p]; ps[8 + p] = a1[p]; }
        }
    }
    __syncthreads();

    if (act && kh == 0) {
        const unsigned long long* ps = part + (lt * 32 + lane) * 16;
        #pragma unroll
        for (int p = 0; p < 8; p++) {
            a0[p] = addf2(a0[p], ps[p]);
            a1[p] = addf2(a1[p], ps[8 + p]);
        }
        float bv0 = v0 ? __ldg(bias + n0) : 0.f;
        float bv1 = v1 ? __ldg(bias + n1) : 0.f;
        #pragma unroll
        for (int b = 0; b < 16; b++) {
            float z0 = lohi(a0[b >> 1], b & 1) + bv0;
            float z1 = lohi(a1[b >> 1], b & 1) + bv1;
            unsigned long long c0 = v0 ? (((unsigned long long)forder(z0) << 32) |
                                          (unsigned long long)(0xFFFFFFFFu - (unsigned)j0)) : 0ull;
            unsigned long long c1 = v1 ? (((unsigned long long)forder(z1) << 32) |
                                          (unsigned long long)(0xFFFFFFFFu - (unsigned)j1)) : 0ull;
            unsigned long long c = c0 > c1 ? c0 : c1;
            #pragma unroll
            for (int o = 16; o; o >>= 1) {
                unsigned long long q = __shfl_xor_sync(0xffffffffu, c, o);
                if (q > c) c = q;
            }
            if (lane == 0) atomicMax(&g_s.pack[b * 3 + isec], c);
        }
    }

    // update-weight sigmoid on otherwise-idle high blocks
    if ((int)blockIdx.x >= NB - 3) {
        int t = ((int)blockIdx.x - (NB - 3)) * 16 + w;
        if (t < 48) {
            int b = t / 3, ii = t - b * 3;
            float a = 0.f;
            for (int k = lane; k < 512; k += 32)
                a = fmaf(__ldcg(yu + b * 512 + k), __ldg(W_uw + k * 3 + ii), a);
            #pragma unroll
            for (int o = 16; o; o >>= 1) a += __shfl_xor_sync(0xffffffffu, a, o);
            if (lane == 0) g_s.updw[t] = 1.f / (1.f + __expf(-a));
        }
    }
}

// ---------------- persistent mega kernel ----------------
__global__ void __launch_bounds__(512, 1) mega_kernel(
    const float* __restrict__ inputs, const float* __restrict__ memory,
    const float* __restrict__ r_w1, const float* __restrict__ r_b1,
    const float* __restrict__ r_w2, const float* __restrict__ r_b2,
    const float* __restrict__ W_read, const float* __restrict__ b_read,
    const float* __restrict__ u_w1, const float* __restrict__ u_b1,
    const float* __restrict__ u_w2, const float* __restrict__ u_b2,
    const float* __restrict__ W_uw, const float* __restrict__ b_uw,
    const float* __restrict__ um_w1, const float* __restrict__ um_b1,
    const float* __restrict__ um_w2, const float* __restrict__ um_b2,
    const float* __restrict__ W_um, const float* __restrict__ b_um,
    const float* __restrict__ am_w1, const float* __restrict__ am_b1,
    const float* __restrict__ am_w2, const float* __restrict__ am_b2,
    const float* __restrict__ W_am, const float* __restrict__ b_am,
    float* __restrict__ out, int NB) {
    extern __shared__ float sm[];
    const int tid = threadIdx.x;
    const int bx = blockIdx.x;
    Scratch* S = &g_s;

    // P0: stage-1 GEMMs for fa_r and fa_u + init pack/m
    if (bx < 32)
        gemm_phase(sm, bx, inputs, 512, 512, nullptr, 0, 0, r_w1, r_b1, 512,
                   S->tr, 512, 0, false, nullptr, 0, 0, nullptr, 0, nullptr, nullptr);
    else if (bx < 64)
        gemm_phase(sm, bx - 32, inputs, 512, 512, nullptr, 0, 0, u_w1, u_b1, 512,
                   S->tu, 512, 0, false, nullptr, 0, 0, nullptr, 0, nullptr, nullptr);
    else if (bx == 64) {
        for (int i = tid; i < 48; i += 512) S->pack[i] = 0ull;
    } else if (bx == 65) {
        for (int i = tid; i < 16 * 256; i += 512) S->m[i] = 0.f;
    }
    gridbar(NB);

    // P1: stage-2 (softmax + gemm + x-mul) for fa_r and fa_u
    if (bx < 32)
        gemm_phase(sm, bx, S->tr, 512, 512, nullptr, 0, 0, r_w2, r_b2, 512,
                   S->yr, 512, 1, true, inputs, 512, 512, nullptr, 0, nullptr, nullptr);
    else if (bx < 64)
        gemm_phase(sm, bx - 32, S->tu, 512, 512, nullptr, 0, 0, u_w2, u_b2, 512,
                   S->yu, 512, 1, true, inputs, 512, 512, nullptr, 0, nullptr, nullptr);
    gridbar(NB);

    // P2: big read GEMM + fused max/argmax (+ updw sigmoid on spare blocks)
    read_phase(sm, NB, S->yr, W_read, b_read, S->yu, W_uw, b_uw);
    gridbar(NB);

    // P3: unpack + gather memory rows + readw
    if (bx < 48) {
        int b = bx / 3, ii = bx - b * 3;
        unsigned long long p = __ldcg(&S->pack[b * 3 + ii]);
        unsigned jn = 0xFFFFFFFFu - (unsigned)(p & 0xFFFFFFFFull);
        if (tid == 0) S->readw[b * 3 + ii] = tanhf(forder_inv((unsigned)(p >> 32)));
        const float* src = memory + ((long)b * 10000 + jn) * 256;
        for (int c = tid; c < 256; c += 512)
            S->rall[b * 768 + ii * 256 + c] = __ldg(src + c);
    }
    gridbar(NB);

    for (int i = 0; i < 3; i++) {
        // fa_um stage 1: cat(r_i, inputs) @ um_w1 + b1  (K=768, N=768)
        if (bx < 48)
            gemm_phase(sm, bx, S->rall + i * 256, 768, 256, inputs, 512, 512,
                       um_w1, um_b1, 768, S->tr, 768, 0, false,
                       nullptr, 0, 0, nullptr, 0, nullptr, nullptr);
        gridbar(NB);
        // fa_um stage 2
        if (bx < 48)
            gemm_phase(sm, bx, S->tr, 768, 768, nullptr, 0, 0,
                       um_w2, um_b2, 768, S->yum, 768, 1, true,
                       S->rall + i * 256, 768, 256, inputs, 512, nullptr, nullptr);
        gridbar(NB);
        // r update: rcur = u*relu(yum@W_um+b_um) + (1-u)*r_i  (K=768, N=256)
        if (bx < 16)
            gemm_phase(sm, bx, S->yum, 768, 768, nullptr, 0, 0,
                       W_um, b_um, 256, S->rcur, 256, 2, false,
                       S->rall + i * 256, 768, 256, nullptr, 0, S->updw + i, nullptr);
        gridbar(NB);
        // fa_am stage 1: cat(rcur, m) @ am_w1 + b1  (K=512, N=512)
        if (bx < 32)
            gemm_phase(sm, bx, S->rcur, 256, 256, S->m, 256, 256,
                       am_w1, am_b1, 512, S->tr, 512, 0, false,
                       nullptr, 0, 0, nullptr, 0, nullptr, nullptr);
        gridbar(NB);
        // fa_am stage 2
        if (bx < 32)
            gemm_phase(sm, bx, S->tr, 512, 512, nullptr, 0, 0,
                       am_w2, am_b2, 512, S->yr, 512, 1, true,
                       S->rcur, 256, 256, S->m, 256, nullptr, nullptr);
        gridbar(NB);
        // m update: m = readw*relu(yam@W_am+b_am)  (K=512, N=256) (+final tanh)
        if (bx < 16)
            gemm_phase(sm, bx, S->yr, 512, 512, nullptr, 0, 0,
                       W_am, b_am, 256, S->m, 256, 3, false,
                       nullptr, 0, 0, nullptr, 0, S->readw + i,
                       (i == 2) ? out : nullptr);
        gridbar(NB);
    }
}

// ---------------- host launcher ----------------
extern "C" void kernel_launch(void* const* d_in, const int* in_sizes, int n_in,
                              void* d_out, int out_size) {
    const float* inputs = (const float*)d_in[0];
    const float* memory = (const float*)d_in[1];
    const float* r_w1 = (const float*)d_in[2];
    const float* r_b1 = (const float*)d_in[3];
    const float* r_w2 = (const float*)d_in[4];
    const float* r_b2 = (const float*)d_in[5];
    const float* W_read = (const float*)d_in[6];
    const float* b_read = (const float*)d_in[7];
    const float* u_w1 = (const float*)d_in[8];
    const float* u_b1 = (const float*)d_in[9];
    const float* u_w2 = (const float*)d_in[10];
    const float* u_b2 = (const float*)d_in[11];
    const float* W_uw = (const float*)d_in[12];
    const float* b_uw = (const float*)d_in[13];
    const float* um_w1 = (const float*)d_in[14];
    const float* um_b1 = (const float*)d_in[15];
    const float* um_w2 = (const float*)d_in[16];
    const float* um_b2 = (const float*)d_in[17];
    const float* W_um = (const float*)d_in[18];
    const float* b_um = (const float*)d_in[19];
    const float* am_w1 = (const float*)d_in[20];
    const float* am_b1 = (const float*)d_in[21];
    const float* am_w2 = (const float*)d_in[22];
    const float* am_b2 = (const float*)d_in[23];
    const float* W_am = (const float*)d_in[24];
    const float* b_am = (const float*)d_in[25];
    float* out = (float*)d_out;

    static int NB = 0;
    if (NB == 0) {
        cudaDeviceGetAttribute(&NB, cudaDevAttrMultiProcessorCount, 0);
        if (NB <= 0) NB = 148;
    }
    const int DSM = 16 * 770 * 4;  // 49280 B (>= read phase's 49152 B)
    static bool attr_set = false;
    if (!attr_set) {
        cudaFuncSetAttribute(mega_kernel, cudaFuncAttributeMaxDynamicSharedMemorySize, DSM);
        attr_set = true;
    }

    mega_kernel<<<NB, 512, DSM>>>(inputs, memory, r_w1, r_b1, r_w2, r_b2,
                                  W_read, b_read, u_w1, u_b1, u_w2, u_b2,
                                  W_uw, b_uw, um_w1, um_b1, um_w2, um_b2,
                                  W_um, b_um, am_w1, am_b1, am_w2, am_b2,
                                  W_am, b_am, out, NB);
}

// round 5
// speedup vs baseline: 3.6037x; 2.0553x over previous
#include <cuda_runtime.h>
#include <cstdint>

#define NTHREADS 512

// ---------------- scratch (no allocations allowed) ----------------
struct Scratch {
    float yr[16 * 512];          // fa_r output rows
    float tum[3 * 16 * 768];     // fa_um stage-1 pre-softmax
    float yum[3 * 16 * 768];     // fa_um output
    float updw[48];              // sigmoid update weights [b*3+i]
    unsigned long long pack[48]; // packed (orderable_max << 32 | ~idx)
};
__device__ Scratch g_s;

__device__ unsigned g_cnt = 0;
__device__ volatile unsigned g_gen = 0;

__device__ __forceinline__ void gridbar(int nb) {
    __syncthreads();
    if (threadIdx.x == 0) {
        unsigned gen = g_gen;
        __threadfence();
        if (atomicAdd(&g_cnt, 1) == (unsigned)(nb - 1)) {
            g_cnt = 0;
            __threadfence();
            g_gen = gen + 1;
        } else {
            while (g_gen == gen) { }
        }
    }
    __syncthreads();
}

__device__ __forceinline__ unsigned int forder(float f) {
    unsigned int u = __float_as_uint(f);
    return (u & 0x80000000u) ? ~u : (u | 0x80000000u);
}
__device__ __forceinline__ float forder_inv(unsigned int u) {
    unsigned int v = (u & 0x80000000u) ? (u & 0x7FFFFFFFu) : ~u;
    return __uint_as_float(v);
}
__device__ __forceinline__ unsigned long long pack2(float f) {
    unsigned u = __float_as_uint(f);
    return ((unsigned long long)u << 32) | (unsigned long long)u;
}
__device__ __forceinline__ void ffma2(unsigned long long& acc, unsigned long long x,
                                      unsigned long long w) {
    asm("fma.rn.f32x2 %0, %1, %2, %0;" : "+l"(acc) : "l"(x), "l"(w));
}
__device__ __forceinline__ unsigned long long addf2(unsigned long long a, unsigned long long b) {
    unsigned long long d;
    asm("add.rn.f32x2 %0, %1, %2;" : "=l"(d) : "l"(a), "l"(b));
    return d;
}
__device__ __forceinline__ float lohi(unsigned long long v, int hi) {
    return __uint_as_float(hi ? (unsigned)(v >> 32) : (unsigned)v);
}

// ---------------- row GEMM: y[j] = dot(xs, W[:,j]) for NT consecutive j ----------------
// All 512 threads participate. Thread owns 4 consecutive j via LDG.128 of W,
// k split (512/(NT/4))-ways, f32x2 packed accumulators, smem cross-k reduce.
// Returns the 4 partial results in a float4 for threads tid < NT/4 (j0 = tid*4).
template <int NT>
__device__ __forceinline__ float4 rowgemm(const float* xs, int K,
                                          const float* __restrict__ W, int ldw,
                                          unsigned long long* part2) {
    constexpr int JQ = NT / 4;
    constexpr int KH = NTHREADS / JQ;
    const int tid = threadIdx.x;
    const int jq = tid & (JQ - 1);
    const int kh = tid / JQ;
    const int kc = K / KH;
    const int k0 = kh * kc;

    unsigned long long a01 = 0ull, a23 = 0ull;
    const float* xp = xs + k0;
    const char* wp = (const char*)(W + (long)k0 * ldw) + (size_t)jq * 16;
    const long wstr = (long)ldw * 4;

    #pragma unroll 2
    for (int t = 0; t < kc; t += 4) {
        float4 xv = *(const float4*)(xp + t);
        ulonglong2 w0 = *(const ulonglong2*)(wp);
        ulonglong2 w1 = *(const ulonglong2*)(wp + wstr);
        ulonglong2 w2 = *(const ulonglong2*)(wp + 2 * wstr);
        ulonglong2 w3 = *(const ulonglong2*)(wp + 3 * wstr);
        ffma2(a01, pack2(xv.x), w0.x); ffma2(a23, pack2(xv.x), w0.y);
        ffma2(a01, pack2(xv.y), w1.x); ffma2(a23, pack2(xv.y), w1.y);
        ffma2(a01, pack2(xv.z), w2.x); ffma2(a23, pack2(xv.z), w2.y);
        ffma2(a01, pack2(xv.w), w3.x); ffma2(a23, pack2(xv.w), w3.y);
        wp += 4 * wstr;
    }
    part2[tid * 2] = a01;
    part2[tid * 2 + 1] = a23;
    __syncthreads();

    float4 r = make_float4(0.f, 0.f, 0.f, 0.f);
    if (tid < JQ) {
        unsigned long long s01 = 0ull, s23 = 0ull;
        #pragma unroll
        for (int h = 0; h < KH; h++) {
            s01 = addf2(s01, part2[(h * JQ + jq) * 2]);
            s23 = addf2(s23, part2[(h * JQ + jq) * 2 + 1]);
        }
        r.x = lohi(s01, 0); r.y = lohi(s01, 1);
        r.z = lohi(s23, 0); r.w = lohi(s23, 1);
    }
    __syncthreads();   // part2 reusable after this
    return r;
}

// ---------------- block-wide softmax over arr[0..L) in smem ----------------
__device__ void blk_softmax(float* arr, int L, float* red) {
    const int tid = threadIdx.x, lane = tid & 31, wid = tid >> 5;
    float mx = -3.4e38f;
    for (int k = tid; k < L; k += NTHREADS) mx = fmaxf(mx, arr[k]);
    #pragma unroll
    for (int o = 16; o; o >>= 1) mx = fmaxf(mx, __shfl_xor_sync(0xffffffffu, mx, o));
    if (lane == 0) red[wid] = mx;
    __syncthreads();
    if (tid < 32) {
        float v = (tid < 16) ? red[tid] : -3.4e38f;
        #pragma unroll
        for (int o = 8; o; o >>= 1) v = fmaxf(v, __shfl_xor_sync(0xffffffffu, v, o));
        if (tid == 0) red[32] = v;
    }
    __syncthreads();
    mx = red[32];
    float s = 0.f;
    for (int k = tid; k < L; k += NTHREADS) s += __expf(arr[k] - mx);
    #pragma unroll
    for (int o = 16; o; o >>= 1) s += __shfl_xor_sync(0xffffffffu, s, o);
    if (lane == 0) red[wid] = s;
    __syncthreads();
    if (tid < 32) {
        float v = (tid < 16) ? red[tid] : 0.f;
        #pragma unroll
        for (int o = 8; o; o >>= 1) v += __shfl_xor_sync(0xffffffffu, v, o);
        if (tid == 0) red[33] = v;
    }
    __syncthreads();
    float inv = 1.f / red[33];
    for (int k = tid; k < L; k += NTHREADS) arr[k] = __expf(arr[k] - mx) * inv;
    __syncthreads();
}

// ---------------- fused fast_attention for one batch row ----------------
// y = x * (softmax(x@w1+b1) @ w2 + b2); writes y to gmem (yout) and/or smem (ys)
__device__ void fa_row(float* sm, const float* __restrict__ x,
                       const float* __restrict__ w1, const float* __restrict__ b1,
                       const float* __restrict__ w2, const float* __restrict__ b2,
                       float* yout, float* ys) {
    float* xs = sm;
    float* hs = sm + 512;
    unsigned long long* part2 = (unsigned long long*)(sm + 1536);
    const int tid = threadIdx.x;

    for (int k = tid; k < 512; k += NTHREADS) xs[k] = __ldg(x + k);
    __syncthreads();

    float4 a = rowgemm<512>(xs, 512, w1, 512, part2);
    if (tid < 128) {
        int j0 = tid * 4;
        float4 bv = *(const float4*)(b1 + j0);
        hs[j0 + 0] = a.x + bv.x;
        hs[j0 + 1] = a.y + bv.y;
        hs[j0 + 2] = a.z + bv.z;
        hs[j0 + 3] = a.w + bv.w;
    }
    __syncthreads();

    blk_softmax(hs, 512, (float*)part2);

    float4 c = rowgemm<512>(hs, 512, w2, 512, part2);
    if (tid < 128) {
        int j0 = tid * 4;
        float4 bv = *(const float4*)(b2 + j0);
        float4 y;
        y.x = xs[j0 + 0] * (c.x + bv.x);
        y.y = xs[j0 + 1] * (c.y + bv.y);
        y.z = xs[j0 + 2] * (c.z + bv.z);
        y.w = xs[j0 + 3] * (c.w + bv.w);
        if (yout) __stcg((float4*)(yout + j0), y);
        if (ys) { ys[j0] = y.x; ys[j0 + 1] = y.y; ys[j0 + 2] = y.z; ys[j0 + 3] = y.w; }
    }
    __syncthreads();
}

// ---------------- big read GEMM + fused max/argmax (FFMA2, proven R2) ----------------
__device__ void read_phase(float* smf,
                           const float* yr,
                           const float* __restrict__ W,
                           const float* __restrict__ bias) {
    const int tid = threadIdx.x;
    unsigned long long* xs2 = (unsigned long long*)smf;      // [k][pair] 512*8
    unsigned long long* part = xs2 + 4096;                   // 4 tiles * 32 * 16

    for (int idx = tid; idx < 4096; idx += NTHREADS) {
        int p = idx / 512, k = idx - p * 512;
        unsigned lo = __float_as_uint(__ldcg(yr + (2 * p) * 512 + k));
        unsigned hi = __float_as_uint(__ldcg(yr + (2 * p + 1) * 512 + k));
        xs2[k * 8 + p] = ((unsigned long long)hi << 32) | (unsigned long long)lo;
    }
    __syncthreads();

    const int w = tid >> 5, lane = tid & 31;
    const int lt = w >> 1, kh = w & 1;
    const int gtile = blockIdx.x * 4 + lt;
    const bool act = (w < 8) && (gtile < 471);

    int isec = 0, j0 = 0, j1 = 0;
    long n0 = 0, n1 = 0;
    bool v0 = false, v1 = false;
    unsigned long long a0[8], a1[8];

    if (act) {
        isec = gtile / 157;
        int t = gtile - isec * 157;
        j0 = t * 64 + lane; j1 = j0 + 32;
        v0 = j0 < 10000; v1 = j1 < 10000;
        n0 = (long)isec * 10000 + j0; n1 = n0 + 32;
        #pragma unroll
        for (int p = 0; p < 8; p++) { a0[p] = 0ull; a1[p] = 0ull; }

        const float* W0 = W + (long)(kh * 256) * 30000;
        const unsigned long long* xk = xs2 + (kh * 256) * 8;
        #pragma unroll 4
        for (int it = 0; it < 256; it++) {
            float wa = v0 ? __ldg(W0 + n0) : 0.f;
            float wb = v1 ? __ldg(W0 + n1) : 0.f;
            unsigned long long wa2 = pack2(wa), wb2 = pack2(wb);
            #pragma unroll
            for (int p = 0; p < 8; p++) {
                unsigned long long xv = xk[p];
                ffma2(a0[p], xv, wa2);
                ffma2(a1[p], xv, wb2);
            }
            W0 += 30000; xk += 8;
        }
        if (kh == 1) {
            unsigned long long* ps = part + (lt * 32 + lane) * 16;
            #pragma unroll
            for (int p = 0; p < 8; p++) { ps[p] = a0[p]; ps[8 + p] = a1[p]; }
        }
    }
    __syncthreads();

    if (act && kh == 0) {
        const unsigned long long* ps = part + (lt * 32 + lane) * 16;
        #pragma unroll
        for (int p = 0; p < 8; p++) {
            a0[p] = addf2(a0[p], ps[p]);
            a1[p] = addf2(a1[p], ps[8 + p]);
        }
        float bv0 = v0 ? __ldg(bias + n0) : 0.f;
        float bv1 = v1 ? __ldg(bias + n1) : 0.f;
        #pragma unroll
        for (int b = 0; b < 16; b++) {
            float z0 = lohi(a0[b >> 1], b & 1) + bv0;
            float z1 = lohi(a1[b >> 1], b & 1) + bv1;
            unsigned long long c0 = v0 ? (((unsigned long long)forder(z0) << 32) |
                                          (unsigned long long)(0xFFFFFFFFu - (unsigned)j0)) : 0ull;
            unsigned long long c1 = v1 ? (((unsigned long long)forder(z1) << 32) |
                                          (unsigned long long)(0xFFFFFFFFu - (unsigned)j1)) : 0ull;
            unsigned long long c = c0 > c1 ? c0 : c1;
            #pragma unroll
            for (int o = 16; o; o >>= 1) {
                unsigned long long q = __shfl_xor_sync(0xffffffffu, c, o);
                if (q > c) c = q;
            }
            if (lane == 0) atomicMax(&g_s.pack[b * 3 + isec], c);
        }
    }
}

// ---------------- persistent mega kernel ----------------
__global__ void __launch_bounds__(NTHREADS, 1) mega_kernel(
    const float* __restrict__ inputs, const float* __restrict__ memory,
    const float* __restrict__ r_w1, const float* __restrict__ r_b1,
    const float* __restrict__ r_w2, const float* __restrict__ r_b2,
    const float* __restrict__ W_read, const float* __restrict__ b_read,
    const float* __restrict__ u_w1, const float* __restrict__ u_b1,
    const float* __restrict__ u_w2, const float* __restrict__ u_b2,
    const float* __restrict__ W_uw, const float* __restrict__ b_uw,
    const float* __restrict__ um_w1, const float* __restrict__ um_b1,
    const float* __restrict__ um_w2, const float* __restrict__ um_b2,
    const float* __restrict__ W_um, const float* __restrict__ b_um,
    const float* __restrict__ am_w1, const float* __restrict__ am_b1,
    const float* __restrict__ am_w2, const float* __restrict__ am_b2,
    const float* __restrict__ W_am, const float* __restrict__ b_am,
    float* __restrict__ out, int NB) {
    extern __shared__ float sm[];
    const int tid = threadIdx.x;
    const int bx = blockIdx.x;

    // ---- P0: fa_r (blocks 0-15), fa_u + updw (16-31), pack init (32) ----
    if (bx < 16) {
        fa_row(sm, inputs + bx * 512, r_w1, r_b1, r_w2, r_b2,
               g_s.yr + bx * 512, nullptr);
    } else if (bx < 32) {
        int b = bx - 16;
        float* ys = sm + 3584;
        fa_row(sm, inputs + b * 512, u_w1, u_b1, u_w2, u_b2, nullptr, ys);
        int wid = tid >> 5, lane = tid & 31;
        if (wid < 3) {
            float acc = 0.f;
            for (int k = lane; k < 512; k += 32)
                acc = fmaf(ys[k], __ldg(W_uw + k * 3 + wid), acc);
            #pragma unroll
            for (int o = 16; o; o >>= 1) acc += __shfl_xor_sync(0xffffffffu, acc, o);
            if (lane == 0) {
                acc += __ldg(b_uw + wid);
                __stcg(&g_s.updw[b * 3 + wid], 1.f / (1.f + __expf(-acc)));
            }
        }
    } else if (bx == 32) {
        for (int i = tid; i < 48; i += NTHREADS) g_s.pack[i] = 0ull;
        __threadfence();
    }
    gridbar(NB);

    // ---- P1: read GEMM + argmax ----
    read_phase(sm, g_s.yr, W_read, b_read);
    gridbar(NB);

    // ---- P2a: fa_um stage 1, all 3 read slots at once (144 blocks) ----
    // block -> (b, i, jc): 48 groups x 3 j-chunks of 256
    __shared__ int s_idx;
    if (bx < 144) {
        int g = bx / 3, jc = bx - g * 3;
        int b = g / 3, i = g - b * 3;
        float* cat = sm;                 // 768: [r_i(256) | inputs(512)]
        unsigned long long* part2 = (unsigned long long*)(sm + 1536);
        if (tid == 0) {
            unsigned long long p = __ldcg(&g_s.pack[b * 3 + i]);
            s_idx = (int)(0xFFFFFFFFu - (unsigned)(p & 0xFFFFFFFFull));
        }
        __syncthreads();
        const float* mrow = memory + ((long)b * 10000 + s_idx) * 256;
        for (int k = tid; k < 256; k += NTHREADS) cat[k] = __ldg(mrow + k);
        for (int k = tid; k < 512; k += NTHREADS) cat[256 + k] = __ldg(inputs + b * 512 + k);
        __syncthreads();
        float4 a = rowgemm<256>(cat, 768, um_w1 + jc * 256, 768, part2);
        if (tid < 64) {
            int j0 = jc * 256 + tid * 4;
            float4 bv = *(const float4*)(um_b1 + j0);
            float4 v = make_float4(a.x + bv.x, a.y + bv.y, a.z + bv.z, a.w + bv.w);
            __stcg((float4*)(g_s.tum + (i * 16 + b) * 768 + j0), v);
        }
    }
    gridbar(NB);

    // ---- P2b: fa_um stage 2 (softmax + gemm + cat-mul); cat persists in smem ----
    if (bx < 144) {
        int g = bx / 3, jc = bx - g * 3;
        int b = g / 3, i = g - b * 3;
        float* cat = sm;
        float* ts = sm + 768;
        unsigned long long* part2 = (unsigned long long*)(sm + 1536);
        for (int k = tid; k < 768; k += NTHREADS)
            ts[k] = __ldcg(g_s.tum + (i * 16 + b) * 768 + k);
        __syncthreads();
        blk_softmax(ts, 768, (float*)part2);
        float4 c = rowgemm<256>(ts, 768, um_w2 + jc * 256, 768, part2);
        if (tid < 64) {
            int j0l = tid * 4;
            int j0 = jc * 256 + j0l;
            float4 bv = *(const float4*)(um_b2 + j0);
            float4 y;
            y.x = cat[j0 + 0] * (c.x + bv.x);
            y.y = cat[j0 + 1] * (c.y + bv.y);
            y.z = cat[j0 + 2] * (c.z + bv.z);
            y.w = cat[j0 + 3] * (c.w + bv.w);
            __stcg((float4*)(g_s.yum + (i * 16 + b) * 768 + j0), y);
        }
    }
    gridbar(NB);

    // ---- P3: full recurrent loop, block-per-row, zero barriers ----
    __shared__ int sidx3[3];
    __shared__ float s_uw[3], s_rw[3];
    if (bx < 16) {
        int b = bx;
        float* rv3 = sm;                 // 768 (3 gathered rows)
        float* yv  = sm + 768;           // 768
        float* c2  = sm + 1536;          // 512: [rcur(256) | m(256)]
        float* ya  = sm + 2048;          // 512
        unsigned long long* part2 = (unsigned long long*)(sm + 2560);

        if (tid < 3) {
            unsigned long long p = __ldcg(&g_s.pack[b * 3 + tid]);
            sidx3[tid] = (int)(0xFFFFFFFFu - (unsigned)(p & 0xFFFFFFFFull));
            s_rw[tid] = tanhf(forder_inv((unsigned)(p >> 32)));
            s_uw[tid] = __ldcg(&g_s.updw[b * 3 + tid]);
        }
        __syncthreads();
        for (int u = tid; u < 768; u += NTHREADS) {
            int i = u >> 8, c = u & 255;
            rv3[u] = __ldg(memory + ((long)b * 10000 + sidx3[i]) * 256 + c);
        }
        for (int j = tid; j < 256; j += NTHREADS) c2[256 + j] = 0.f;
        __syncthreads();

        for (int i = 0; i < 3; i++) {
            for (int k = tid; k < 768; k += NTHREADS)
                yv[k] = __ldcg(g_s.yum + (i * 16 + b) * 768 + k);
            __syncthreads();

            // r update: rc = u*relu(yv@W_um + b_um) + (1-u)*r_i
            float4 a = rowgemm<256>(yv, 768, W_um, 256, part2);
            if (tid < 64) {
                int j0 = tid * 4;
                float u = s_uw[i];
                float4 bv = *(const float4*)(b_um + j0);
                c2[j0 + 0] = u * fmaxf(a.x + bv.x, 0.f) + (1.f - u) * rv3[i * 256 + j0 + 0];
                c2[j0 + 1] = u * fmaxf(a.y + bv.y, 0.f) + (1.f - u) * rv3[i * 256 + j0 + 1];
                c2[j0 + 2] = u * fmaxf(a.z + bv.z, 0.f) + (1.f - u) * rv3[i * 256 + j0 + 2];
                c2[j0 + 3] = u * fmaxf(a.w + bv.w, 0.f) + (1.f - u) * rv3[i * 256 + j0 + 3];
            }
            __syncthreads();

            // fa_am stage 1 on cat2=[rc|m]
            float4 h4 = rowgemm<512>(c2, 512, am_w1, 512, part2);
            if (tid < 128) {
                int j0 = tid * 4;
                float4 bv = *(const float4*)(am_b1 + j0);
                ya[j0 + 0] = h4.x + bv.x; ya[j0 + 1] = h4.y + bv.y;
                ya[j0 + 2] = h4.z + bv.z; ya[j0 + 3] = h4.w + bv.w;
            }
            __syncthreads();
            blk_softmax(ya, 512, (float*)part2);

            // fa_am stage 2: yam = cat2 * (h@w2 + b2)  (in-place into ya)
            float4 c = rowgemm<512>(ya, 512, am_w2, 512, part2);
            if (tid < 128) {
                int j0 = tid * 4;
                float4 bv = *(const float4*)(am_b2 + j0);
                ya[j0 + 0] = c2[j0 + 0] * (c.x + bv.x);
                ya[j0 + 1] = c2[j0 + 1] * (c.y + bv.y);
                ya[j0 + 2] = c2[j0 + 2] * (c.z + bv.z);
                ya[j0 + 3] = c2[j0 + 3] * (c.w + bv.w);
            }
            __syncthreads();

            // m update: m = readw * relu(yam@W_am + b_am)  (+ final tanh out)
            float4 d = rowgemm<256>(ya, 512, W_am, 256, part2);
            if (tid < 64) {
                int j0 = tid * 4;
                float rw = s_rw[i];
                float4 bv = *(const float4*)(b_am + j0);
                float m0 = rw * fmaxf(d.x + bv.x, 0.f);
                float m1 = rw * fmaxf(d.y + bv.y, 0.f);
                float m2 = rw * fmaxf(d.z + bv.z, 0.f);
                float m3 = rw * fmaxf(d.w + bv.w, 0.f);
                c2[256 + j0 + 0] = m0; c2[256 + j0 + 1] = m1;
                c2[256 + j0 + 2] = m2; c2[256 + j0 + 3] = m3;
                if (i == 2) {
                    float4 o = make_float4(tanhf(m0), tanhf(m1), tanhf(m2), tanhf(m3));
                    *(float4*)(out + b * 256 + j0) = o;
                }
            }
            __syncthreads();
        }
    }
}

// ---------------- host launcher ----------------
extern "C" void kernel_launch(void* const* d_in, const int* in_sizes, int n_in,
                              void* d_out, int out_size) {
    const float* inputs = (const float*)d_in[0];
    const float* memory = (const float*)d_in[1];
    const float* r_w1 = (const float*)d_in[2];
    const float* r_b1 = (const float*)d_in[3];
    const float* r_w2 = (const float*)d_in[4];
    const float* r_b2 = (const float*)d_in[5];
    const float* W_read = (const float*)d_in[6];
    const float* b_read = (const float*)d_in[7];
    const float* u_w1 = (const float*)d_in[8];
    const float* u_b1 = (const float*)d_in[9];
    const float* u_w2 = (const float*)d_in[10];
    const float* u_b2 = (const float*)d_in[11];
    const float* W_uw = (const float*)d_in[12];
    const float* b_uw = (const float*)d_in[13];
    const float* um_w1 = (const float*)d_in[14];
    const float* um_b1 = (const float*)d_in[15];
    const float* um_w2 = (const float*)d_in[16];
    const float* um_b2 = (const float*)d_in[17];
    const float* W_um = (const float*)d_in[18];
    const float* b_um = (const float*)d_in[19];
    const float* am_w1 = (const float*)d_in[20];
    const float* am_b1 = (const float*)d_in[21];
    const float* am_w2 = (const float*)d_in[22];
    const float* am_b2 = (const float*)d_in[23];
    const float* W_am = (const float*)d_in[24];
    const float* b_am = (const float*)d_in[25];
    float* out = (float*)d_out;

    static int NB = 0;
    if (NB == 0) {
        cudaDeviceGetAttribute(&NB, cudaDevAttrMultiProcessorCount, 0);
        if (NB <= 0) NB = 148;
    }
    const int DSM = 49280;  // >= P1's 48KB
    static bool attr_set = false;
    if (!attr_set) {
        cudaFuncSetAttribute(mega_kernel, cudaFuncAttributeMaxDynamicSharedMemorySize, DSM);
        attr_set = true;
    }

    mega_kernel<<<NB, NTHREADS, DSM>>>(inputs, memory, r_w1, r_b1, r_w2, r_b2,
                                       W_read, b_read, u_w1, u_b1, u_w2, u_b2,
                                       W_uw, b_uw, um_w1, um_b1, um_w2, um_b2,
                                       W_um, b_um, am_w1, am_b1, am_w2, am_b2,
                                       W_am, b_am, out, NB);
}

// round 6
// speedup vs baseline: 4.2576x; 1.1815x over previous
#include <cuda_runtime.h>
#include <cstdint>

#define NTHREADS 512

// ---------------- scratch (no allocations allowed) ----------------
struct Scratch {
    float yr[16 * 512];          // fa_r output rows
    float tum[3 * 16 * 768];     // fa_um stage-1 pre-softmax
    float yum[3 * 16 * 768];     // fa_um output
    float updw[48];              // sigmoid update weights [b*3+i]
    unsigned long long pack[48]; // packed (orderable_max << 32 | ~idx)
};
__device__ Scratch g_s;

__device__ __forceinline__ unsigned int forder(float f) {
    unsigned int u = __float_as_uint(f);
    return (u & 0x80000000u) ? ~u : (u | 0x80000000u);
}
__device__ __forceinline__ float forder_inv(unsigned int u) {
    unsigned int v = (u & 0x80000000u) ? (u & 0x7FFFFFFFu) : ~u;
    return __uint_as_float(v);
}
__device__ __forceinline__ unsigned long long pack2(float f) {
    unsigned u = __float_as_uint(f);
    return ((unsigned long long)u << 32) | (unsigned long long)u;
}
__device__ __forceinline__ void ffma2(unsigned long long& acc, unsigned long long x,
                                      unsigned long long w) {
    asm("fma.rn.f32x2 %0, %1, %2, %0;" : "+l"(acc) : "l"(x), "l"(w));
}
__device__ __forceinline__ unsigned long long addf2(unsigned long long a, unsigned long long b) {
    unsigned long long d;
    asm("add.rn.f32x2 %0, %1, %2;" : "=l"(d) : "l"(a), "l"(b));
    return d;
}
__device__ __forceinline__ float lohi(unsigned long long v, int hi) {
    return __uint_as_float(hi ? (unsigned)(v >> 32) : (unsigned)v);
}

// ---------------- row GEMM: y[j] = dot(xs, W[:,j]) for NT consecutive j ----------------
template <int NT>
__device__ __forceinline__ float4 rowgemm(const float* xs, int K,
                                          const float* __restrict__ W, int ldw,
                                          unsigned long long* part2) {
    constexpr int JQ = NT / 4;
    constexpr int KH = NTHREADS / JQ;
    const int tid = threadIdx.x;
    const int jq = tid & (JQ - 1);
    const int kh = tid / JQ;
    const int kc = K / KH;
    const int k0 = kh * kc;

    unsigned long long a01 = 0ull, a23 = 0ull;
    const float* xp = xs + k0;
    const char* wp = (const char*)(W + (long)k0 * ldw) + (size_t)jq * 16;
    const long wstr = (long)ldw * 4;

    #pragma unroll 2
    for (int t = 0; t < kc; t += 4) {
        float4 xv = *(const float4*)(xp + t);
        ulonglong2 w0 = *(const ulonglong2*)(wp);
        ulonglong2 w1 = *(const ulonglong2*)(wp + wstr);
        ulonglong2 w2 = *(const ulonglong2*)(wp + 2 * wstr);
        ulonglong2 w3 = *(const ulonglong2*)(wp + 3 * wstr);
        ffma2(a01, pack2(xv.x), w0.x); ffma2(a23, pack2(xv.x), w0.y);
        ffma2(a01, pack2(xv.y), w1.x); ffma2(a23, pack2(xv.y), w1.y);
        ffma2(a01, pack2(xv.z), w2.x); ffma2(a23, pack2(xv.z), w2.y);
        ffma2(a01, pack2(xv.w), w3.x); ffma2(a23, pack2(xv.w), w3.y);
        wp += 4 * wstr;
    }
    part2[tid * 2] = a01;
    part2[tid * 2 + 1] = a23;
    __syncthreads();

    float4 r = make_float4(0.f, 0.f, 0.f, 0.f);
    if (tid < JQ) {
        unsigned long long s01 = 0ull, s23 = 0ull;
        #pragma unroll
        for (int h = 0; h < KH; h++) {
            s01 = addf2(s01, part2[(h * JQ + jq) * 2]);
            s23 = addf2(s23, part2[(h * JQ + jq) * 2 + 1]);
        }
        r.x = lohi(s01, 0); r.y = lohi(s01, 1);
        r.z = lohi(s23, 0); r.w = lohi(s23, 1);
    }
    __syncthreads();
    return r;
}

// ---------------- block-wide softmax over arr[0..L) in smem ----------------
__device__ void blk_softmax(float* arr, int L, float* red) {
    const int tid = threadIdx.x, lane = tid & 31, wid = tid >> 5;
    float mx = -3.4e38f;
    for (int k = tid; k < L; k += NTHREADS) mx = fmaxf(mx, arr[k]);
    #pragma unroll
    for (int o = 16; o; o >>= 1) mx = fmaxf(mx, __shfl_xor_sync(0xffffffffu, mx, o));
    if (lane == 0) red[wid] = mx;
    __syncthreads();
    if (tid < 32) {
        float v = (tid < 16) ? red[tid] : -3.4e38f;
        #pragma unroll
        for (int o = 8; o; o >>= 1) v = fmaxf(v, __shfl_xor_sync(0xffffffffu, v, o));
        if (tid == 0) red[32] = v;
    }
    __syncthreads();
    mx = red[32];
    float s = 0.f;
    for (int k = tid; k < L; k += NTHREADS) s += __expf(arr[k] - mx);
    #pragma unroll
    for (int o = 16; o; o >>= 1) s += __shfl_xor_sync(0xffffffffu, s, o);
    if (lane == 0) red[wid] = s;
    __syncthreads();
    if (tid < 32) {
        float v = (tid < 16) ? red[tid] : 0.f;
        #pragma unroll
        for (int o = 8; o; o >>= 1) v += __shfl_xor_sync(0xffffffffu, v, o);
        if (tid == 0) red[33] = v;
    }
    __syncthreads();
    float inv = 1.f / red[33];
    for (int k = tid; k < L; k += NTHREADS) arr[k] = __expf(arr[k] - mx) * inv;
    __syncthreads();
}

// ---------------- fused fast_attention for one batch row ----------------
__device__ void fa_row(float* sm, const float* __restrict__ x,
                       const float* __restrict__ w1, const float* __restrict__ b1,
                       const float* __restrict__ w2, const float* __restrict__ b2,
                       float* yout, float* ys) {
    float* xs = sm;
    float* hs = sm + 512;
    unsigned long long* part2 = (unsigned long long*)(sm + 1536);
    const int tid = threadIdx.x;

    for (int k = tid; k < 512; k += NTHREADS) xs[k] = __ldg(x + k);
    __syncthreads();

    float4 a = rowgemm<512>(xs, 512, w1, 512, part2);
    if (tid < 128) {
        int j0 = tid * 4;
        float4 bv = *(const float4*)(b1 + j0);
        hs[j0 + 0] = a.x + bv.x;
        hs[j0 + 1] = a.y + bv.y;
        hs[j0 + 2] = a.z + bv.z;
        hs[j0 + 3] = a.w + bv.w;
    }
    __syncthreads();

    blk_softmax(hs, 512, (float*)part2);

    float4 c = rowgemm<512>(hs, 512, w2, 512, part2);
    if (tid < 128) {
        int j0 = tid * 4;
        float4 bv = *(const float4*)(b2 + j0);
        float4 y;
        y.x = xs[j0 + 0] * (c.x + bv.x);
        y.y = xs[j0 + 1] * (c.y + bv.y);
        y.z = xs[j0 + 2] * (c.z + bv.z);
        y.w = xs[j0 + 3] * (c.w + bv.w);
        if (yout) __stcg((float4*)(yout + j0), y);
        if (ys) { ys[j0] = y.x; ys[j0 + 1] = y.y; ys[j0 + 2] = y.z; ys[j0 + 3] = y.w; }
    }
    __syncthreads();
}

// ================= K0: fa_r (0-15), fa_u + updw (16-31), pack init =================
__global__ void __launch_bounds__(NTHREADS, 1) k0_front(
    const float* __restrict__ inputs,
    const float* __restrict__ r_w1, const float* __restrict__ r_b1,
    const float* __restrict__ r_w2, const float* __restrict__ r_b2,
    const float* __restrict__ u_w1, const float* __restrict__ u_b1,
    const float* __restrict__ u_w2, const float* __restrict__ u_b2,
    const float* __restrict__ W_uw, const float* __restrict__ b_uw) {
    extern __shared__ float sm[];
    const int tid = threadIdx.x;
    const int bx = blockIdx.x;

    if (bx == 0 && tid < 48) g_s.pack[tid] = 0ull;

    if (bx < 16) {
        fa_row(sm, inputs + bx * 512, r_w1, r_b1, r_w2, r_b2,
               g_s.yr + bx * 512, nullptr);
    } else {
        int b = bx - 16;
        float* ys = sm + 3584;
        fa_row(sm, inputs + b * 512, u_w1, u_b1, u_w2, u_b2, nullptr, ys);
        int wid = tid >> 5, lane = tid & 31;
        if (wid < 3) {
            float acc = 0.f;
            for (int k = lane; k < 512; k += 32)
                acc = fmaf(ys[k], __ldg(W_uw + k * 3 + wid), acc);
            #pragma unroll
            for (int o = 16; o; o >>= 1) acc += __shfl_xor_sync(0xffffffffu, acc, o);
            if (lane == 0) {
                acc += __ldg(b_uw + wid);
                __stcg(&g_s.updw[b * 3 + wid], 1.f / (1.f + __expf(-acc)));
            }
        }
    }
}

// ================= K1: read GEMM + fused max/argmax =================
// 471 tiles of 64 cols. 152 blocks: first 15 take 4 tiles, rest take 3.
// Per block: 16 warps = 4 tile-slots x 4-way k-split (128 k each).
__global__ void __launch_bounds__(NTHREADS, 1) k1_read(
    const float* __restrict__ W, const float* __restrict__ bias) {
    extern __shared__ float smf[];
    unsigned long long* xs2 = (unsigned long long*)smf;  // [k][pair] 512*8
    unsigned long long* part = xs2 + 4096;               // 4 slots * 3 * 32 * 16

    const int tid = threadIdx.x;
    const int bx = blockIdx.x;

    for (int idx = tid; idx < 4096; idx += NTHREADS) {
        int p = idx / 512, k = idx - p * 512;
        unsigned lo = __float_as_uint(__ldcg(g_s.yr + (2 * p) * 512 + k));
        unsigned hi = __float_as_uint(__ldcg(g_s.yr + (2 * p + 1) * 512 + k));
        xs2[k * 8 + p] = ((unsigned long long)hi << 32) | (unsigned long long)lo;
    }
    __syncthreads();

    const int w = tid >> 5, lane = tid & 31;
    const int ts = w >> 2, kh = w & 3;
    const int cnt = (bx < 15) ? 4 : 3;
    const int start = (bx < 15) ? 4 * bx : 60 + 3 * (bx - 15);
    const bool act = ts < cnt;

    int isec = 0, j0 = 0, j1 = 0;
    long n0 = 0, n1 = 0;
    bool v0 = false, v1 = false;
    unsigned long long a0[8], a1[8];

    if (act) {
        int gtile = start + ts;
        isec = gtile / 157;
        int t = gtile - isec * 157;
        j0 = t * 64 + lane; j1 = j0 + 32;
        v0 = j0 < 10000; v1 = j1 < 10000;
        n0 = (long)isec * 10000 + j0; n1 = n0 + 32;
        #pragma unroll
        for (int p = 0; p < 8; p++) { a0[p] = 0ull; a1[p] = 0ull; }

        const float* W0 = W + (long)(kh * 128) * 30000;
        const unsigned long long* xk = xs2 + (kh * 128) * 8;
        #pragma unroll 4
        for (int it = 0; it < 128; it++) {
            float wa = v0 ? __ldg(W0 + n0) : 0.f;
            float wb = v1 ? __ldg(W0 + n1) : 0.f;
            unsigned long long wa2 = pack2(wa), wb2 = pack2(wb);
            #pragma unroll
            for (int p = 0; p < 8; p++) {
                unsigned long long xv = xk[p];
                ffma2(a0[p], xv, wa2);
                ffma2(a1[p], xv, wb2);
            }
            W0 += 30000; xk += 8;
        }
        if (kh > 0) {
            unsigned long long* ps = part + ((ts * 3 + (kh - 1)) * 32 + lane) * 16;
            #pragma unroll
            for (int p = 0; p < 8; p++) { ps[p] = a0[p]; ps[8 + p] = a1[p]; }
        }
    }
    __syncthreads();

    if (act && kh == 0) {
        #pragma unroll
        for (int h = 0; h < 3; h++) {
            const unsigned long long* ps = part + ((ts * 3 + h) * 32 + lane) * 16;
            #pragma unroll
            for (int p = 0; p < 8; p++) {
                a0[p] = addf2(a0[p], ps[p]);
                a1[p] = addf2(a1[p], ps[8 + p]);
            }
        }
        float bv0 = v0 ? __ldg(bias + n0) : 0.f;
        float bv1 = v1 ? __ldg(bias + n1) : 0.f;
        #pragma unroll
        for (int b = 0; b < 16; b++) {
            float z0 = lohi(a0[b >> 1], b & 1) + bv0;
            float z1 = lohi(a1[b >> 1], b & 1) + bv1;
            unsigned long long c0 = v0 ? (((unsigned long long)forder(z0) << 32) |
                                          (unsigned long long)(0xFFFFFFFFu - (unsigned)j0)) : 0ull;
            unsigned long long c1 = v1 ? (((unsigned long long)forder(z1) << 32) |
                                          (unsigned long long)(0xFFFFFFFFu - (unsigned)j1)) : 0ull;
            unsigned long long c = c0 > c1 ? c0 : c1;
            #pragma unroll
            for (int o = 16; o; o >>= 1) {
                unsigned long long q = __shfl_xor_sync(0xffffffffu, c, o);
                if (q > c) c = q;
            }
            if (lane == 0) atomicMax(&g_s.pack[b * 3 + isec], c);
        }
    }
}

// ================= K2a: fa_um stage 1 (144 blocks: 48 groups x 3 j-chunks) ==========
__global__ void __launch_bounds__(NTHREADS, 1) k2a_um1(
    const float* __restrict__ inputs, const float* __restrict__ memory,
    const float* __restrict__ um_w1, const float* __restrict__ um_b1) {
    extern __shared__ float sm[];
    __shared__ int s_idx;
    const int tid = threadIdx.x;
    const int bx = blockIdx.x;
    int g = bx / 3, jc = bx - g * 3;
    int b = g / 3, i = g - b * 3;
    float* cat = sm;
    unsigned long long* part2 = (unsigned long long*)(sm + 1536);
    if (tid == 0) {
        unsigned long long p = __ldcg(&g_s.pack[b * 3 + i]);
        s_idx = (int)(0xFFFFFFFFu - (unsigned)(p & 0xFFFFFFFFull));
    }
    __syncthreads();
    const float* mrow = memory + ((long)b * 10000 + s_idx) * 256;
    for (int k = tid; k < 256; k += NTHREADS) cat[k] = __ldg(mrow + k);
    for (int k = tid; k < 512; k += NTHREADS) cat[256 + k] = __ldg(inputs + b * 512 + k);
    __syncthreads();
    float4 a = rowgemm<256>(cat, 768, um_w1 + jc * 256, 768, part2);
    if (tid < 64) {
        int j0 = jc * 256 + tid * 4;
        float4 bv = *(const float4*)(um_b1 + j0);
        float4 v = make_float4(a.x + bv.x, a.y + bv.y, a.z + bv.z, a.w + bv.w);
        __stcg((float4*)(g_s.tum + (i * 16 + b) * 768 + j0), v);
    }
}

// ================= K2b: fa_um stage 2 (softmax + gemm + cat-mul) ==========
__global__ void __launch_bounds__(NTHREADS, 1) k2b_um2(
    const float* __restrict__ inputs, const float* __restrict__ memory,
    const float* __restrict__ um_w2, const float* __restrict__ um_b2) {
    extern __shared__ float sm[];
    __shared__ int s_idx;
    const int tid = threadIdx.x;
    const int bx = blockIdx.x;
    int g = bx / 3, jc = bx - g * 3;
    int b = g / 3, i = g - b * 3;
    float* cat = sm;
    float* ts = sm + 768;
    unsigned long long* part2 = (unsigned long long*)(sm + 1536);
    if (tid == 0) {
        unsigned long long p = __ldcg(&g_s.pack[b * 3 + i]);
        s_idx = (int)(0xFFFFFFFFu - (unsigned)(p & 0xFFFFFFFFull));
    }
    __syncthreads();
    const float* mrow = memory + ((long)b * 10000 + s_idx) * 256;
    for (int k = tid; k < 256; k += NTHREADS) cat[k] = __ldg(mrow + k);
    for (int k = tid; k < 512; k += NTHREADS) cat[256 + k] = __ldg(inputs + b * 512 + k);
    for (int k = tid; k < 768; k += NTHREADS)
        ts[k] = __ldcg(g_s.tum + (i * 16 + b) * 768 + k);
    __syncthreads();
    blk_softmax(ts, 768, (float*)part2);
    float4 c = rowgemm<256>(ts, 768, um_w2 + jc * 256, 768, part2);
    if (tid < 64) {
        int j0 = jc * 256 + tid * 4;
        float4 bv = *(const float4*)(um_b2 + j0);
        float4 y;
        y.x = cat[j0 + 0] * (c.x + bv.x);
        y.y = cat[j0 + 1] * (c.y + bv.y);
        y.z = cat[j0 + 2] * (c.z + bv.z);
        y.w = cat[j0 + 3] * (c.w + bv.w);
        __stcg((float4*)(g_s.yum + (i * 16 + b) * 768 + j0), y);
    }
}

// ================= K3: recurrent loop, block-per-row =================
__global__ void __launch_bounds__(NTHREADS, 1) k3_loop(
    const float* __restrict__ memory,
    const float* __restrict__ W_um, const float* __restrict__ b_um,
    const float* __restrict__ am_w1, const float* __restrict__ am_b1,
    const float* __restrict__ am_w2, const float* __restrict__ am_b2,
    const float* __restrict__ W_am, const float* __restrict__ b_am,
    float* __restrict__ out) {
    extern __shared__ float sm[];
    __shared__ int sidx3[3];
    __shared__ float s_uw[3], s_rw[3];
    const int tid = threadIdx.x;
    const int b = blockIdx.x;

    float* rv3 = sm;                 // 768
    float* yv  = sm + 768;           // 768
    float* c2  = sm + 1536;          // 512: [rcur | m]
    float* ya  = sm + 2048;          // 512
    unsigned long long* part2 = (unsigned long long*)(sm + 2560);

    if (tid < 3) {
        unsigned long long p = __ldcg(&g_s.pack[b * 3 + tid]);
        sidx3[tid] = (int)(0xFFFFFFFFu - (unsigned)(p & 0xFFFFFFFFull));
        s_rw[tid] = tanhf(forder_inv((unsigned)(p >> 32)));
        s_uw[tid] = __ldcg(&g_s.updw[b * 3 + tid]);
    }
    __syncthreads();
    for (int u = tid; u < 768; u += NTHREADS) {
        int i = u >> 8, c = u & 255;
        rv3[u] = __ldg(memory + ((long)b * 10000 + sidx3[i]) * 256 + c);
    }
    for (int j = tid; j < 256; j += NTHREADS) c2[256 + j] = 0.f;
    __syncthreads();

    for (int i = 0; i < 3; i++) {
        for (int k = tid; k < 768; k += NTHREADS)
            yv[k] = __ldcg(g_s.yum + (i * 16 + b) * 768 + k);
        __syncthreads();

        float4 a = rowgemm<256>(yv, 768, W_um, 256, part2);
        if (tid < 64) {
            int j0 = tid * 4;
            float u = s_uw[i];
            float4 bv = *(const float4*)(b_um + j0);
            c2[j0 + 0] = u * fmaxf(a.x + bv.x, 0.f) + (1.f - u) * rv3[i * 256 + j0 + 0];
            c2[j0 + 1] = u * fmaxf(a.y + bv.y, 0.f) + (1.f - u) * rv3[i * 256 + j0 + 1];
            c2[j0 + 2] = u * fmaxf(a.z + bv.z, 0.f) + (1.f - u) * rv3[i * 256 + j0 + 2];
            c2[j0 + 3] = u * fmaxf(a.w + bv.w, 0.f) + (1.f - u) * rv3[i * 256 + j0 + 3];
        }
        __syncthreads();

        float4 h4 = rowgemm<512>(c2, 512, am_w1, 512, part2);
        if (tid < 128) {
            int j0 = tid * 4;
            float4 bv = *(const float4*)(am_b1 + j0);
            ya[j0 + 0] = h4.x + bv.x; ya[j0 + 1] = h4.y + bv.y;
            ya[j0 + 2] = h4.z + bv.z; ya[j0 + 3] = h4.w + bv.w;
        }
        __syncthreads();
        blk_softmax(ya, 512, (float*)part2);

        float4 c = rowgemm<512>(ya, 512, am_w2, 512, part2);
        if (tid < 128) {
            int j0 = tid * 4;
            float4 bv = *(const float4*)(am_b2 + j0);
            ya[j0 + 0] = c2[j0 + 0] * (c.x + bv.x);
            ya[j0 + 1] = c2[j0 + 1] * (c.y + bv.y);
            ya[j0 + 2] = c2[j0 + 2] * (c.z + bv.z);
            ya[j0 + 3] = c2[j0 + 3] * (c.w + bv.w);
        }
        __syncthreads();

        float4 d = rowgemm<256>(ya, 512, W_am, 256, part2);
        if (tid < 64) {
            int j0 = tid * 4;
            float rw = s_rw[i];
            float4 bv = *(const float4*)(b_am + j0);
            float m0 = rw * fmaxf(d.x + bv.x, 0.f);
            float m1 = rw * fmaxf(d.y + bv.y, 0.f);
            float m2 = rw * fmaxf(d.z + bv.z, 0.f);
            float m3 = rw * fmaxf(d.w + bv.w, 0.f);
            c2[256 + j0 + 0] = m0; c2[256 + j0 + 1] = m1;
            c2[256 + j0 + 2] = m2; c2[256 + j0 + 3] = m3;
            if (i == 2) {
                float4 o = make_float4(tanhf(m0), tanhf(m1), tanhf(m2), tanhf(m3));
                *(float4*)(out + b * 256 + j0) = o;
            }
        }
        __syncthreads();
    }
}

// ---------------- host launcher ----------------
extern "C" void kernel_launch(void* const* d_in, const int* in_sizes, int n_in,
                              void* d_out, int out_size) {
    const float* inputs = (const float*)d_in[0];
    const float* memory = (const float*)d_in[1];
    const float* r_w1 = (const float*)d_in[2];
    const float* r_b1 = (const float*)d_in[3];
    const float* r_w2 = (const float*)d_in[4];
    const float* r_b2 = (const float*)d_in[5];
    const float* W_read = (const float*)d_in[6];
    const float* b_read = (const float*)d_in[7];
    const float* u_w1 = (const float*)d_in[8];
    const float* u_b1 = (const float*)d_in[9];
    const float* u_w2 = (const float*)d_in[10];
    const float* u_b2 = (const float*)d_in[11];
    const float* W_uw = (const float*)d_in[12];
    const float* b_uw = (const float*)d_in[13];
    const float* um_w1 = (const float*)d_in[14];
    const float* um_b1 = (const float*)d_in[15];
    const float* um_w2 = (const float*)d_in[16];
    const float* um_b2 = (const float*)d_in[17];
    const float* W_um = (const float*)d_in[18];
    const float* b_um = (const float*)d_in[19];
    const float* am_w1 = (const float*)d_in[20];
    const float* am_b1 = (const float*)d_in[21];
    const float* am_w2 = (const float*)d_in[22];
    const float* am_b2 = (const float*)d_in[23];
    const float* W_am = (const float*)d_in[24];
    const float* b_am = (const float*)d_in[25];
    float* out = (float*)d_out;

    const int DSM0 = 16384;   // k0: 4096 floats
    const int DSM1 = 81920;   // k1: xs2 32KB + part 48KB
    const int DSM2 = 14336;   // k2: 3584 floats
    const int DSM3 = 18432;   // k3: 4608 floats
    static bool attr_set = false;
    if (!attr_set) {
        cudaFuncSetAttribute(k0_front, cudaFuncAttributeMaxDynamicSharedMemorySize, DSM0);
        cudaFuncSetAttribute(k1_read,  cudaFuncAttributeMaxDynamicSharedMemorySize, DSM1);
        cudaFuncSetAttribute(k2a_um1,  cudaFuncAttributeMaxDynamicSharedMemorySize, DSM2);
        cudaFuncSetAttribute(k2b_um2,  cudaFuncAttributeMaxDynamicSharedMemorySize, DSM2);
        cudaFuncSetAttribute(k3_loop,  cudaFuncAttributeMaxDynamicSharedMemorySize, DSM3);
        attr_set = true;
    }

    k0_front<<<32, NTHREADS, DSM0>>>(inputs, r_w1, r_b1, r_w2, r_b2,
                                     u_w1, u_b1, u_w2, u_b2, W_uw, b_uw);
    k1_read<<<152, NTHREADS, DSM1>>>(W_read, b_read);
    k2a_um1<<<144, NTHREADS, DSM2>>>(inputs, memory, um_w1, um_b1);
    k2b_um2<<<144, NTHREADS, DSM2>>>(inputs, memory, um_w2, um_b2);
    k3_loop<<<16, NTHREADS, DSM3>>>(memory, W_um, b_um, am_w1, am_b1,
                                    am_w2, am_b2, W_am, b_am, out);
}